// round 2
// baseline (speedup 1.0000x reference)
#include <cuda_runtime.h>
#include <math.h>

#define NT   4096
#define NAr  4096
#define NSr  1024
#define NALL 9216
#define FEAT 128
#define COM  64
#define MPD  64
#define NCLS 3
#define CAP  128   // max nnz per adjacency row (expected ~20, p=0.005)

// ---------------- static device scratch (no allocations allowed) -------------
// 7 big 4096x4096 matrices: 0=G 1=P 2=Q 3=FA(topoA then f_h_A) 4=FS 5=SA(sim_rA then s_h_A) 6=SS
__device__ float g_big[7ll * NT * NT];

// small scratch, float
#define OFF_XN    0                         // 4096*256
#define OFF_SIMS  (OFF_XN   + NT*256)       // 1024*1024
#define OFF_TOPOS (OFF_SIMS + NSr*NSr)      // 4096*1024
#define OFF_FPA   (OFF_TOPOS+ NT*NSr)       // 4096*128
#define OFF_FPS   (OFF_FPA  + NT*FEAT)      // 4096*128
#define OFF_THA   (OFF_FPS  + NT*FEAT)      // 4096*64
#define OFF_THS   (OFF_THA  + NT*COM)       // 4096*64
#define OFF_H0    (OFF_THS  + NT*COM)       // 4096*64
#define OFF_X1    (OFF_H0   + NT*COM)       // 4096*64
#define OFF_H2    (OFF_X1   + NT*COM)       // 4096*3
#define OFF_CS    (OFF_H2   + NT*NCLS)      // 7*4096
#define OFF_COEF  (OFF_CS   + 7*NT)         // 7*4096
#define OFF_CT    (OFF_COEF + 7*NT)         // 4096
#define OFF_PART  (OFF_CT   + NT)           // 16*4096
#define SMALL_TOT (OFF_PART + 16*NT)
__device__ float g_small[SMALL_TOT];

#define OFF_IDXA 0
#define OFF_CNTA (OFF_IDXA + NT*CAP)
#define OFF_IDXS (OFF_CNTA + NT)
#define OFF_CNTS (OFF_IDXS + NT*CAP)
#define IBUF_TOT (OFF_CNTS + NT)
__device__ int g_ibuf[IBUF_TOT];

// ---------------- kernels ----------------------------------------------------

// Build per-head weighted + L2-row-normalized features: dst[N, H*D]
__global__ void prep_norm_kernel(const float* __restrict__ src, const float* __restrict__ w,
                                 float* __restrict__ dst, int N, int D, int H)
{
    int row  = blockIdx.x * (blockDim.x >> 5) + (threadIdx.x >> 5);
    int lane = threadIdx.x & 31;
    if (row >= N) return;
    int HD = H * D;
    for (int h = 0; h < H; h++) {
        float ss = 0.f;
        for (int d = lane; d < D; d += 32) {
            float v = src[(size_t)row * D + d] * w[h * D + d];
            ss += v * v;
        }
        #pragma unroll
        for (int o = 16; o; o >>= 1) ss += __shfl_xor_sync(0xffffffffu, ss, o);
        float inv = 1.f / fmaxf(sqrtf(ss), 1e-12f);
        for (int d = lane; d < D; d += 32)
            dst[(size_t)row * HD + h * D + d] = src[(size_t)row * D + d] * w[h * D + d] * inv;
    }
}

__device__ __forceinline__ float thrf(float v, float scale, float th)
{
    v *= scale;
    return (v < th) ? 0.f : v;
}

// C = threshold(scale * X @ X^T). Symmetric: only lower-left blocks computed, both tiles written.
__global__ void __launch_bounds__(256, 1)
simgemm_kernel(const float* __restrict__ X, float* __restrict__ C,
               int N, int K, float scale, float th)
{
    const int bx = blockIdx.x, by = blockIdx.y;
    if (bx < by) return;
    const int m0 = by * 128, n0 = bx * 128;

    __shared__ float As[16][128];
    __shared__ float Bs[16][128];

    const int tid = threadIdx.x;
    const int ldr = tid >> 2;            // 0..63
    const int ldc = (tid & 3) << 2;      // 0,4,8,12
    const int ty  = tid >> 4;            // 0..15
    const int tx  = tid & 15;            // 0..15
    const int ry  = ty << 3;
    const int rx  = tx << 3;

    float acc[8][8];
    #pragma unroll
    for (int i = 0; i < 8; i++)
        #pragma unroll
        for (int j = 0; j < 8; j++) acc[i][j] = 0.f;

    for (int k0 = 0; k0 < K; k0 += 16) {
        float4 a0 = *(const float4*)(X + (size_t)(m0 + ldr)      * K + k0 + ldc);
        float4 a1 = *(const float4*)(X + (size_t)(m0 + ldr + 64) * K + k0 + ldc);
        float4 b0 = *(const float4*)(X + (size_t)(n0 + ldr)      * K + k0 + ldc);
        float4 b1 = *(const float4*)(X + (size_t)(n0 + ldr + 64) * K + k0 + ldc);
        __syncthreads();
        As[ldc+0][ldr]    = a0.x; As[ldc+1][ldr]    = a0.y; As[ldc+2][ldr]    = a0.z; As[ldc+3][ldr]    = a0.w;
        As[ldc+0][ldr+64] = a1.x; As[ldc+1][ldr+64] = a1.y; As[ldc+2][ldr+64] = a1.z; As[ldc+3][ldr+64] = a1.w;
        Bs[ldc+0][ldr]    = b0.x; Bs[ldc+1][ldr]    = b0.y; Bs[ldc+2][ldr]    = b0.z; Bs[ldc+3][ldr]    = b0.w;
        Bs[ldc+0][ldr+64] = b1.x; Bs[ldc+1][ldr+64] = b1.y; Bs[ldc+2][ldr+64] = b1.z; Bs[ldc+3][ldr+64] = b1.w;
        __syncthreads();
        #pragma unroll
        for (int k = 0; k < 16; k++) {
            float4 av0 = *(const float4*)&As[k][ry];
            float4 av1 = *(const float4*)&As[k][ry + 4];
            float4 bv0 = *(const float4*)&Bs[k][rx];
            float4 bv1 = *(const float4*)&Bs[k][rx + 4];
            float a[8] = {av0.x,av0.y,av0.z,av0.w,av1.x,av1.y,av1.z,av1.w};
            float b[8] = {bv0.x,bv0.y,bv0.z,bv0.w,bv1.x,bv1.y,bv1.z,bv1.w};
            #pragma unroll
            for (int i = 0; i < 8; i++)
                #pragma unroll
                for (int j = 0; j < 8; j++)
                    acc[i][j] = fmaf(a[i], b[j], acc[i][j]);
        }
    }
    // normal tile
    #pragma unroll
    for (int i = 0; i < 8; i++) {
        #pragma unroll
        for (int j = 0; j < 8; j += 4) {
            float4 v = make_float4(thrf(acc[i][j],   scale, th), thrf(acc[i][j+1], scale, th),
                                   thrf(acc[i][j+2], scale, th), thrf(acc[i][j+3], scale, th));
            *(float4*)(C + (size_t)(m0 + ry + i) * N + (n0 + rx + j)) = v;
        }
    }
    if (bx > by) {   // mirrored tile (symmetric)
        #pragma unroll
        for (int j = 0; j < 8; j++) {
            #pragma unroll
            for (int i = 0; i < 8; i += 4) {
                float4 v = make_float4(thrf(acc[i][j],   scale, th), thrf(acc[i+1][j], scale, th),
                                       thrf(acc[i+2][j], scale, th), thrf(acc[i+3][j], scale, th));
                *(float4*)(C + (size_t)(n0 + rx + j) * N + (m0 + ry + i)) = v;
            }
        }
    }
}

// Deterministic ballot-compacted nonzero index list per target row of an adjacency block.
__global__ void build_idx_kernel(const float* __restrict__ adj, int col_off, int NR,
                                 int* __restrict__ idx, int* __restrict__ cnt)
{
    int i = blockIdx.x;
    const float* r = adj + (size_t)i * NALL + col_off;
    int lane = threadIdx.x;
    int count = 0;
    for (int base = 0; base < NR; base += 32) {
        float v = r[base + lane];
        unsigned m = __ballot_sync(0xffffffffu, v != 0.f);
        int pre = __popc(m & ((1u << lane) - 1u));
        if (v != 0.f && (count + pre) < CAP) idx[(size_t)i * CAP + count + pre] = base + lane;
        count += __popc(m);
    }
    if (lane == 0) cnt[i] = min(count, CAP);
}

// out[i, :cols] = sum over listed rows of src (exact: adjacency is 0/1)
__global__ void gather_sum_kernel(const float* __restrict__ src, int lds,
                                  const int* __restrict__ idx, const int* __restrict__ cnt,
                                  float* __restrict__ out, int ldo)
{
    int i = blockIdx.y;
    int j = ((blockIdx.x * blockDim.x + threadIdx.x) << 2);
    int c = cnt[i];
    const int* ip = idx + (size_t)i * CAP;
    float4 s = make_float4(0.f, 0.f, 0.f, 0.f);
    for (int t = 0; t < c; t++) {
        float4 v = *(const float4*)(src + (size_t)ip[t] * lds + j);
        s.x += v.x; s.y += v.y; s.z += v.z; s.w += v.w;
    }
    *(float4*)(out + (size_t)i * ldo + j) = s;
}

// C[M,64] = A[M,K] @ B[K,64] (+bias) (optional relu)
__global__ void __launch_bounds__(256)
gemm_n64_kernel(const float* __restrict__ A, const float* __restrict__ B,
                const float* __restrict__ bias, float* __restrict__ C,
                int M, int K, int relu)
{
    __shared__ float As[32][64];
    __shared__ float Bs[32][64];
    int tid = threadIdx.x;
    int m0  = blockIdx.x * 64;
    int ar  = tid >> 3;            // 0..31
    int ac  = (tid & 7) << 2;      // 0..28
    int br  = tid >> 4;            // 0..15
    int bc  = (tid & 15) << 2;     // 0..60
    int ty  = tid >> 4, tx = tid & 15;

    float acc[4][4];
    #pragma unroll
    for (int i = 0; i < 4; i++)
        #pragma unroll
        for (int j = 0; j < 4; j++) acc[i][j] = 0.f;

    for (int k0 = 0; k0 < K; k0 += 32) {
        float4 a0 = *(const float4*)(A + (size_t)(m0 + ar)      * K + k0 + ac);
        float4 a1 = *(const float4*)(A + (size_t)(m0 + ar + 32) * K + k0 + ac);
        float4 b0 = *(const float4*)(B + (size_t)(k0 + br)      * 64 + bc);
        float4 b1 = *(const float4*)(B + (size_t)(k0 + br + 16) * 64 + bc);
        __syncthreads();
        As[ac+0][ar]    = a0.x; As[ac+1][ar]    = a0.y; As[ac+2][ar]    = a0.z; As[ac+3][ar]    = a0.w;
        As[ac+0][ar+32] = a1.x; As[ac+1][ar+32] = a1.y; As[ac+2][ar+32] = a1.z; As[ac+3][ar+32] = a1.w;
        *(float4*)&Bs[br][bc]      = b0;
        *(float4*)&Bs[br + 16][bc] = b1;
        __syncthreads();
        #pragma unroll
        for (int k = 0; k < 32; k++) {
            float4 av = *(const float4*)&As[k][ty << 2];
            float4 bv = *(const float4*)&Bs[k][tx << 2];
            float a[4] = {av.x, av.y, av.z, av.w};
            float b[4] = {bv.x, bv.y, bv.z, bv.w};
            #pragma unroll
            for (int i = 0; i < 4; i++)
                #pragma unroll
                for (int j = 0; j < 4; j++)
                    acc[i][j] = fmaf(a[i], b[j], acc[i][j]);
        }
    }
    int r = m0 + (ty << 2), c = tx << 2;
    #pragma unroll
    for (int i = 0; i < 4; i++)
        #pragma unroll
        for (int j = 0; j < 4; j++) {
            float v = acc[i][j] + (bias ? bias[c + j] : 0.f);
            if (relu) v = fmaxf(v, 0.f);
            C[(size_t)(r + i) * 64 + c + j] = v;
        }
}

// two-stage deterministic column |.| sums over [NT,NT]
__global__ void colsum_part_kernel(const float* __restrict__ M_, float* __restrict__ part)
{
    int j  = blockIdx.x * 256 + threadIdx.x;
    int i0 = blockIdx.y * 256;
    float s = 0.f;
    #pragma unroll 4
    for (int i = i0; i < i0 + 256; i++) s += fabsf(M_[(size_t)i * NT + j]);
    part[(size_t)blockIdx.y * NT + j] = s;
}
__global__ void colsum_fin_kernel(const float* __restrict__ part, float* __restrict__ c)
{
    int j = blockIdx.x * 256 + threadIdx.x;
    float s = 0.f;
    #pragma unroll
    for (int r = 0; r < 16; r++) s += part[(size_t)r * NT + j];
    c[j] = s;
}

// per-column combine coefficients for the fused channel attention.
// Handles all-zero columns in base matrices (e.g. nodes with no S-relation
// neighbors): the post-normalization colsum of an inner channel is
// sa0*u(csA)+sa1*u(csB), not 1, where u(x)=1 iff column is nonzero.
__global__ void coefs_kernel(const float* __restrict__ sgw, const float* __restrict__ ffw,
                             const float* __restrict__ f4w,
                             const float* __restrict__ cs, float* __restrict__ coef)
{
    int j = blockIdx.x * 256 + threadIdx.x;
    float m2 = fmaxf(sgw[0], sgw[1]);
    float e0 = expf(sgw[0] - m2), e1 = expf(sgw[1] - m2);
    float sa0 = e0 / (e0 + e1), sa1 = e1 / (e0 + e1);
    float mf = fmaxf(ffw[0], ffw[1]);
    float f0 = expf(ffw[0] - mf), f1 = expf(ffw[1] - mf);
    float fa0 = f0 / (f0 + f1), fa1 = f1 / (f0 + f1);
    float m4 = fmaxf(fmaxf(f4w[0], f4w[1]), fmaxf(f4w[2], f4w[3]));
    float w0 = expf(f4w[0] - m4), w1 = expf(f4w[1] - m4), w2 = expf(f4w[2] - m4), w3 = expf(f4w[3] - m4);
    float ws = w0 + w1 + w2 + w3;
    w0 /= ws; w1 /= ws; w2 /= ws; w3 /= ws;

    float csG  = cs[0 * NT + j], csP  = cs[1 * NT + j], csQ  = cs[2 * NT + j];
    float csFA = cs[3 * NT + j], csFS = cs[4 * NT + j];
    float csSA = cs[5 * NT + j], csSS = cs[6 * NT + j];
    // nonzero colsums are >= threshold (0.1); exact zeros stay exact
    float uP  = (csP  > 0.05f) ? 1.f : 0.f;
    float uQ  = (csQ  > 0.05f) ? 1.f : 0.f;
    float uFA = (csFA > 0.05f) ? 1.f : 0.f;
    float uFS = (csFS > 0.05f) ? 1.f : 0.f;
    float uSA = (csSA > 0.05f) ? 1.f : 0.f;
    float uSS = (csSS > 0.05f) ? 1.f : 0.f;
    float dSem = fmaxf(sa0 * uP  + sa1 * uQ,  1e-12f);
    float dFp  = fmaxf(fa0 * uFA + fa1 * uFS, 1e-12f);
    float dSt  = fmaxf(fa0 * uSA + fa1 * uSS, 1e-12f);

    coef[0 * NT + j] = w0 / fmaxf(csG, 1e-12f);
    coef[1 * NT + j] = w1 * sa0 / (fmaxf(csP,  1e-12f) * dSem);
    coef[2 * NT + j] = w1 * sa1 / (fmaxf(csQ,  1e-12f) * dSem);
    coef[3 * NT + j] = w2 * fa0 / (fmaxf(csFA, 1e-12f) * dFp);
    coef[4 * NT + j] = w2 * fa1 / (fmaxf(csFS, 1e-12f) * dFp);
    coef[5 * NT + j] = w3 * fa0 / (fmaxf(csSA, 1e-12f) * dSt);
    coef[6 * NT + j] = w3 * fa1 / (fmaxf(csSS, 1e-12f) * dSt);
}

// A_pre = sum_m coef_m[j] * M_m[i,j] — fuses sem_g/fp_g/sim_tt/new_adj channel attentions
__global__ void combine_kernel(const float* __restrict__ G,  const float* __restrict__ P,
                               const float* __restrict__ Q,  const float* __restrict__ FA,
                               const float* __restrict__ FS, const float* __restrict__ SA,
                               const float* __restrict__ SS, const float* __restrict__ coef,
                               float* __restrict__ out)
{
    size_t e = ((size_t)blockIdx.x * 256 + threadIdx.x) << 2;
    int j = (int)(e & (NT - 1));
    float4 r = make_float4(0.f, 0.f, 0.f, 0.f);
#define ACC(buf, m) { float4 v = *(const float4*)((buf) + e);                 \
                      float4 k = *(const float4*)(coef + (m) * NT + j);       \
                      r.x = fmaf(k.x, v.x, r.x); r.y = fmaf(k.y, v.y, r.y);   \
                      r.z = fmaf(k.z, v.z, r.z); r.w = fmaf(k.w, v.w, r.w); }
    ACC(G, 0) ACC(P, 1) ACC(Q, 2) ACC(FA, 3) ACC(FS, 4) ACC(SA, 5) ACC(SS, 6)
#undef ACC
    *(float4*)(out + e) = r;
}

// in-place A = A + A^T (paired 32x32 tiles)
__global__ void symadd_kernel(float* __restrict__ A)
{
    int bi = blockIdx.y, bj = blockIdx.x;
    if (bj < bi) return;
    __shared__ float T1[32][33], T2[32][33];
    int x = threadIdx.x, y0 = threadIdx.y;
    for (int y = y0; y < 32; y += 8) T1[y][x] = A[(size_t)(bi * 32 + y) * NT + bj * 32 + x];
    if (bi != bj)
        for (int y = y0; y < 32; y += 8) T2[y][x] = A[(size_t)(bj * 32 + y) * NT + bi * 32 + x];
    __syncthreads();
    if (bi == bj) {
        for (int y = y0; y < 32; y += 8)
            A[(size_t)(bi * 32 + y) * NT + bj * 32 + x] = T1[y][x] + T1[x][y];
    } else {
        for (int y = y0; y < 32; y += 8)
            A[(size_t)(bi * 32 + y) * NT + bj * 32 + x] = T1[y][x] + T2[x][y];
        for (int y = y0; y < 32; y += 8)
            A[(size_t)(bj * 32 + y) * NT + bi * 32 + x] = T2[y][x] + T1[x][y];
    }
}

__global__ void scale_cols_kernel(float* __restrict__ A, const float* __restrict__ cT)
{
    size_t e = ((size_t)blockIdx.x * 256 + threadIdx.x) << 2;
    int j = (int)(e & (NT - 1));
    float4 v = *(float4*)(A + e);
    float4 c = *(const float4*)(cT + j);
    v.x /= fmaxf(c.x, 1e-12f); v.y /= fmaxf(c.y, 1e-12f);
    v.z /= fmaxf(c.z, 1e-12f); v.w /= fmaxf(c.w, 1e-12f);
    *(float4*)(A + e) = v;
}

// H2[i,0:3] = X1[i,:] @ W2
__global__ void x1w2_kernel(const float* __restrict__ X1, const float* __restrict__ W2,
                            float* __restrict__ H2)
{
    int i = blockIdx.x * 256 + threadIdx.x;
    if (i >= NT) return;
    float s0 = 0.f, s1 = 0.f, s2 = 0.f;
    #pragma unroll 8
    for (int k = 0; k < COM; k++) {
        float x = X1[(size_t)i * COM + k];
        s0 = fmaf(x, W2[k * 3 + 0], s0);
        s1 = fmaf(x, W2[k * 3 + 1], s1);
        s2 = fmaf(x, W2[k * 3 + 2], s2);
    }
    H2[i * 3 + 0] = s0; H2[i * 3 + 1] = s1; H2[i * 3 + 2] = s2;
}

// logits row i = log_softmax( NA[i,:] @ H2 + b2 )
__global__ void logits_kernel(const float* __restrict__ A, const float* __restrict__ H2,
                              const float* __restrict__ b2, float* __restrict__ out)
{
    int i = blockIdx.x, tid = threadIdx.x;
    const float* row = A + (size_t)i * NT;
    float s0 = 0.f, s1 = 0.f, s2 = 0.f;
    for (int k = tid; k < NT; k += 256) {
        float a = row[k];
        s0 = fmaf(a, H2[k * 3 + 0], s0);
        s1 = fmaf(a, H2[k * 3 + 1], s1);
        s2 = fmaf(a, H2[k * 3 + 2], s2);
    }
    #pragma unroll
    for (int o = 16; o; o >>= 1) {
        s0 += __shfl_xor_sync(0xffffffffu, s0, o);
        s1 += __shfl_xor_sync(0xffffffffu, s1, o);
        s2 += __shfl_xor_sync(0xffffffffu, s2, o);
    }
    __shared__ float sh[3][8];
    int w = tid >> 5, l = tid & 31;
    if (l == 0) { sh[0][w] = s0; sh[1][w] = s1; sh[2][w] = s2; }
    __syncthreads();
    if (tid == 0) {
        float x0 = 0.f, x1 = 0.f, x2 = 0.f;
        #pragma unroll
        for (int t = 0; t < 8; t++) { x0 += sh[0][t]; x1 += sh[1][t]; x2 += sh[2][t]; }
        x0 += b2[0]; x1 += b2[1]; x2 += b2[2];
        float m  = fmaxf(x0, fmaxf(x1, x2));
        float ls = logf(expf(x0 - m) + expf(x1 - m) + expf(x2 - m));
        out[i * 3 + 0] = x0 - m - ls;
        out[i * 3 + 1] = x1 - m - ls;
        out[i * 3 + 2] = x2 - m - ls;
    }
}

// ---------------- host orchestration ----------------------------------------

extern "C" void kernel_launch(void* const* d_in, const int* in_sizes, int n_in,
                              void* d_out, int out_size)
{
    const float* features  = (const float*)d_in[0];
    const float* adj_ori   = (const float*)d_in[1];
    const float* mp_pap    = (const float*)d_in[2];
    const float* mp_psp    = (const float*)d_in[3];
    // d_in[4]=enc_W, d_in[5]=enc_b : dead in the reference graph
    const float* fgo_w     = (const float*)d_in[6];
    const float* fpo_w     = (const float*)d_in[7];
    const float* sgg_pap_w = (const float*)d_in[8];
    const float* sgg_psp_w = (const float*)d_in[9];
    const float* sg_agg_w  = (const float*)d_in[10];
    const float* f_agg_f_w = (const float*)d_in[11];
    const float* f_agg_w   = (const float*)d_in[12];
    const float* topo_W_a  = (const float*)d_in[13];
    const float* topo_b_a  = (const float*)d_in[14];
    const float* topo_W_s  = (const float*)d_in[15];
    const float* topo_b_s  = (const float*)d_in[16];
    const float* fgt_w_a   = (const float*)d_in[17];
    const float* fgt_w_s   = (const float*)d_in[18];
    const float* gcn_W1    = (const float*)d_in[19];
    const float* gcn_b1    = (const float*)d_in[20];
    const float* gcn_W2    = (const float*)d_in[21];
    const float* gcn_b2    = (const float*)d_in[22];
    (void)in_sizes; (void)n_in; (void)out_size;

    float* out   = (float*)d_out;
    float* NAdj  = out + (size_t)NT * NCLS;   // [4096,4096] new_adj section

    float* big = nullptr; float* sm = nullptr; int* ib = nullptr;
    cudaGetSymbolAddress((void**)&big, g_big);
    cudaGetSymbolAddress((void**)&sm,  g_small);
    cudaGetSymbolAddress((void**)&ib,  g_ibuf);

    float* G   = big + 0ll * NT * NT;
    float* P   = big + 1ll * NT * NT;
    float* Q   = big + 2ll * NT * NT;
    float* FAb = big + 3ll * NT * NT;   // topo_A, then f_h_A
    float* FSb = big + 4ll * NT * NT;
    float* SAb = big + 5ll * NT * NT;   // sim_r_A, then s_h_A
    float* SSb = big + 6ll * NT * NT;

    float* XN   = sm + OFF_XN;
    float* SIMS = sm + OFF_SIMS;
    float* TOPS = sm + OFF_TOPOS;
    float* FPA  = sm + OFF_FPA;
    float* FPS  = sm + OFF_FPS;
    float* THA  = sm + OFF_THA;
    float* THS  = sm + OFF_THS;
    float* H0   = sm + OFF_H0;
    float* X1   = sm + OFF_X1;
    float* H2   = sm + OFF_H2;
    float* CS   = sm + OFF_CS;
    float* COEF = sm + OFF_COEF;
    float* CT   = sm + OFF_CT;
    float* PART = sm + OFF_PART;

    int* IDXA = ib + OFF_IDXA; int* CNTA = ib + OFF_CNTA;
    int* IDXS = ib + OFF_IDXS; int* CNTS = ib + OFF_CNTS;

    dim3 gSim(32, 32), gSimS(8, 8), bSym(32, 8);

    // ---- g_targ: graph_gen(features[0:4096], fgo_w, 0.1) ----
    prep_norm_kernel<<<NT / 4, 128>>>(features, fgo_w, XN, NT, FEAT, 2);
    simgemm_kernel<<<gSim, 256>>>(XN, G, NT, 256, 0.5f, 0.1f);

    // ---- sem_pap / sem_psp ----
    prep_norm_kernel<<<NT / 4, 128>>>(mp_pap, sgg_pap_w, XN, NT, MPD, 2);
    simgemm_kernel<<<gSim, 256>>>(XN, P, NT, 128, 0.5f, 0.1f);
    prep_norm_kernel<<<NT / 4, 128>>>(mp_psp, sgg_psp_w, XN, NT, MPD, 2);
    simgemm_kernel<<<gSim, 256>>>(XN, Q, NT, 128, 0.5f, 0.1f);

    // ---- relation A ----
    prep_norm_kernel<<<NT / 4, 128>>>(features + (size_t)NT * FEAT, fgo_w, XN, NAr, FEAT, 2);
    simgemm_kernel<<<gSim, 256>>>(XN, SAb, NAr, 256, 0.5f, 0.1f);      // sim_r_A -> SAb
    build_idx_kernel<<<NT, 32>>>(adj_ori, NT, NAr, IDXA, CNTA);
    gather_sum_kernel<<<dim3(4, NT), 256>>>(SAb, NAr, IDXA, CNTA, FAb, NAr);   // topo_A -> FAb
    gather_sum_kernel<<<dim3(1, NT), 32>>>(features + (size_t)NT * FEAT, FEAT, IDXA, CNTA, FPA, FEAT);
    gemm_n64_kernel<<<NT / 64, 256>>>(FAb, topo_W_a, topo_b_a, THA, NT, NAr, 0); // topo_hid_A
    prep_norm_kernel<<<NT / 4, 128>>>(FPA, fpo_w, XN, NT, FEAT, 2);
    simgemm_kernel<<<gSim, 256>>>(XN, FAb, NT, 256, 0.5f, 0.2f);       // f_h_A (overwrites topo_A)
    prep_norm_kernel<<<NT / 4, 128>>>(THA, fgt_w_a, XN, NT, COM, 2);
    simgemm_kernel<<<gSim, 256>>>(XN, SAb, NT, 128, 0.5f, 0.1f);       // s_h_A (overwrites sim_r_A)

    // ---- relation S ----
    prep_norm_kernel<<<NSr / 4, 128>>>(features + (size_t)(NT + NAr) * FEAT, fgo_w, XN, NSr, FEAT, 2);
    simgemm_kernel<<<gSimS, 256>>>(XN, SIMS, NSr, 256, 0.5f, 0.1f);    // sim_r_S
    build_idx_kernel<<<NT, 32>>>(adj_ori, NT + NAr, NSr, IDXS, CNTS);
    gather_sum_kernel<<<dim3(1, NT), 256>>>(SIMS, NSr, IDXS, CNTS, TOPS, NSr);  // topo_S
    gather_sum_kernel<<<dim3(1, NT), 32>>>(features + (size_t)(NT + NAr) * FEAT, FEAT, IDXS, CNTS, FPS, FEAT);
    gemm_n64_kernel<<<NT / 64, 256>>>(TOPS, topo_W_s, topo_b_s, THS, NT, NSr, 0); // topo_hid_S
    prep_norm_kernel<<<NT / 4, 128>>>(FPS, fpo_w, XN, NT, FEAT, 2);
    simgemm_kernel<<<gSim, 256>>>(XN, FSb, NT, 256, 0.5f, 0.2f);       // f_h_S
    prep_norm_kernel<<<NT / 4, 128>>>(THS, fgt_w_s, XN, NT, COM, 2);
    simgemm_kernel<<<gSim, 256>>>(XN, SSb, NT, 128, 0.5f, 0.1f);       // s_h_S

    // ---- column sums of the 7 base matrices ----
    const float* mats[7] = {G, P, Q, FAb, FSb, SAb, SSb};
    for (int m = 0; m < 7; m++) {
        colsum_part_kernel<<<dim3(16, 16), 256>>>(mats[m], PART);
        colsum_fin_kernel<<<16, 256>>>(PART, CS + m * NT);
    }
    coefs_kernel<<<16, 256>>>(sg_agg_w, f_agg_f_w, f_agg_w, CS, COEF);

    // ---- fused channel attention -> A_pre, symmetrize, column-normalize ----
    combine_kernel<<<(NT * (size_t)NT) / (256 * 4), 256>>>(G, P, Q, FAb, FSb, SAb, SSb, COEF, NAdj);
    symadd_kernel<<<dim3(128, 128), bSym>>>(NAdj);
    colsum_part_kernel<<<dim3(16, 16), 256>>>(NAdj, PART);
    colsum_fin_kernel<<<16, 256>>>(PART, CT);
    scale_cols_kernel<<<(NT * (size_t)NT) / (256 * 4), 256>>>(NAdj, CT);

    // ---- GCN ----
    gemm_n64_kernel<<<NT / 64, 256>>>(features, gcn_W1, nullptr, H0, NT, FEAT, 0);  // fmat @ W1
    gemm_n64_kernel<<<NT / 64, 256>>>(NAdj, H0, gcn_b1, X1, NT, NT, 1);             // relu(NA@H0+b1)
    x1w2_kernel<<<16, 256>>>(X1, gcn_W2, H2);                                        // X1 @ W2
    logits_kernel<<<NT, 256>>>(NAdj, H2, gcn_b2, out);                               // log_softmax(NA@H2+b2)
}

// round 3
// speedup vs baseline: 1.5508x; 1.5508x over previous
#include <cuda_runtime.h>
#include <math.h>

#define NT   4096
#define NAr  4096
#define NSr  1024
#define NALL 9216
#define FEAT 128
#define COM  64
#define MPD  64
#define NCLS 3
#define CAP  128   // max nnz per adjacency row (expected ~20, p=0.005)

// ---------------- static device scratch (no allocations allowed) -------------
// 7 big 4096x4096 matrices: 0=G 1=P 2=Q 3=FA 4=FS 5=SA(sim_rA then s_h_A) 6=SS
__device__ float g_big[7ll * NT * NT];

// small scratch, float
#define OFF_XN    0                          // 4096*256
#define OFF_SIMS  (OFF_XN   + NT*256)        // 1024*1024
#define OFF_FPA   (OFF_SIMS + NSr*NSr)       // 4096*128
#define OFF_FPS   (OFF_FPA  + NT*FEAT)       // 4096*128
#define OFF_THA   (OFF_FPS  + NT*FEAT)       // 4096*64
#define OFF_THS   (OFF_THA  + NT*COM)        // 4096*64
#define OFF_SWA   (OFF_THS  + NT*COM)        // 4096*64
#define OFF_SWS   (OFF_SWA  + NT*COM)        // 1024*64
#define OFF_H0    (OFF_SWS  + NSr*COM)       // 4096*64
#define OFF_X1    (OFF_H0   + NT*COM)        // 4096*64
#define OFF_H2    (OFF_X1   + NT*COM)        // 4096*3
#define OFF_CS    (OFF_H2   + NT*NCLS)       // 7*4096
#define OFF_COEF  (OFF_CS   + 7*NT)          // 7*4096
#define OFF_CT0   (OFF_COEF + 7*NT)          // 4096
#define OFF_CT    (OFF_CT0  + NT)            // 4096
#define OFF_ROWP  (OFF_CT   + NT)            // 4096*4
#define OFF_CSP   (OFF_ROWP + 4*NT)          // 7*32*4096
#define OFF_SPART (OFF_CSP  + 7*32*NT)       // 8*4096*64
#define SMALL_TOT (OFF_SPART + 8*NT*64)
__device__ float g_small[SMALL_TOT];

#define OFF_IDXA 0
#define OFF_CNTA (OFF_IDXA + NT*CAP)
#define OFF_IDXS (OFF_CNTA + NT)
#define OFF_CNTS (OFF_IDXS + NT*CAP)
#define IBUF_TOT (OFF_CNTS + NT)
__device__ int g_ibuf[IBUF_TOT];

// ---------------- kernels ----------------------------------------------------

// Build per-head weighted + L2-row-normalized features: dst[N, H*D]
__global__ void prep_norm_kernel(const float* __restrict__ src, const float* __restrict__ w,
                                 float* __restrict__ dst, int N, int D, int H)
{
    int row  = blockIdx.x * (blockDim.x >> 5) + (threadIdx.x >> 5);
    int lane = threadIdx.x & 31;
    if (row >= N) return;
    int HD = H * D;
    for (int h = 0; h < H; h++) {
        float ss = 0.f;
        for (int d = lane; d < D; d += 32) {
            float v = src[(size_t)row * D + d] * w[h * D + d];
            ss += v * v;
        }
        #pragma unroll
        for (int o = 16; o; o >>= 1) ss += __shfl_xor_sync(0xffffffffu, ss, o);
        float inv = 1.f / fmaxf(sqrtf(ss), 1e-12f);
        for (int d = lane; d < D; d += 32)
            dst[(size_t)row * HD + h * D + d] = src[(size_t)row * D + d] * w[h * D + d] * inv;
    }
}

__device__ __forceinline__ float thrf(float v, float scale, float th)
{
    v *= scale;
    return (v < th) ? 0.f : v;
}

// C = threshold(scale * X @ X^T). Triangular-packed grid, double-buffered smem.
// Optional per-row-block column-sum partials (csPart[32][N]) of the thresholded
// output, covering both direct and mirrored tiles (deterministic).
__global__ void __launch_bounds__(256, 2)
simgemm_kernel(const float* __restrict__ X, float* __restrict__ C,
               int N, int K, float scale, float th,
               float* __restrict__ csPart, int nBlk)
{
    // decode linear block id -> (by, bx) with bx >= by
    int idx = blockIdx.x;
    float nb2 = nBlk + 0.5f;
    int by = (int)(nb2 - sqrtf(fmaxf(nb2 * nb2 - 2.0f * idx, 0.f)));
    if (by < 0) by = 0;
    if (by > nBlk - 1) by = nBlk - 1;
    while (by > 0 && (by * nBlk - (by * (by - 1)) / 2) > idx) by--;
    while (((by + 1) * nBlk - ((by + 1) * by) / 2) <= idx) by++;
    int bx = by + (idx - (by * nBlk - (by * (by - 1)) / 2));

    const int m0 = by * 128, n0 = bx * 128;

    __shared__ float As[2][16][128];
    __shared__ float Bs[2][16][128];

    const int tid = threadIdx.x;
    const int ldr = tid >> 2;            // 0..63
    const int ldc = (tid & 3) << 2;      // 0,4,8,12
    const int ty  = tid >> 4;            // 0..15
    const int tx  = tid & 15;            // 0..15
    const int ry  = ty << 3;
    const int rx  = tx << 3;

    float acc[8][8];
    #pragma unroll
    for (int i = 0; i < 8; i++)
        #pragma unroll
        for (int j = 0; j < 8; j++) acc[i][j] = 0.f;

    float4 a0, a1, b0, b1;

#define LOADG(k0) {                                                             \
    a0 = *(const float4*)(X + (size_t)(m0 + ldr)      * K + (k0) + ldc);        \
    a1 = *(const float4*)(X + (size_t)(m0 + ldr + 64) * K + (k0) + ldc);        \
    b0 = *(const float4*)(X + (size_t)(n0 + ldr)      * K + (k0) + ldc);        \
    b1 = *(const float4*)(X + (size_t)(n0 + ldr + 64) * K + (k0) + ldc); }

#define STORES(bf) {                                                            \
    As[bf][ldc+0][ldr]    = a0.x; As[bf][ldc+1][ldr]    = a0.y;                 \
    As[bf][ldc+2][ldr]    = a0.z; As[bf][ldc+3][ldr]    = a0.w;                 \
    As[bf][ldc+0][ldr+64] = a1.x; As[bf][ldc+1][ldr+64] = a1.y;                 \
    As[bf][ldc+2][ldr+64] = a1.z; As[bf][ldc+3][ldr+64] = a1.w;                 \
    Bs[bf][ldc+0][ldr]    = b0.x; Bs[bf][ldc+1][ldr]    = b0.y;                 \
    Bs[bf][ldc+2][ldr]    = b0.z; Bs[bf][ldc+3][ldr]    = b0.w;                 \
    Bs[bf][ldc+0][ldr+64] = b1.x; Bs[bf][ldc+1][ldr+64] = b1.y;                 \
    Bs[bf][ldc+2][ldr+64] = b1.z; Bs[bf][ldc+3][ldr+64] = b1.w; }

#define COMPUTE(bf) {                                                           \
    _Pragma("unroll")                                                           \
    for (int k = 0; k < 16; k++) {                                              \
        float4 av0 = *(const float4*)&As[bf][k][ry];                            \
        float4 av1 = *(const float4*)&As[bf][k][ry + 4];                        \
        float4 bv0 = *(const float4*)&Bs[bf][k][rx];                            \
        float4 bv1 = *(const float4*)&Bs[bf][k][rx + 4];                        \
        float a[8] = {av0.x,av0.y,av0.z,av0.w,av1.x,av1.y,av1.z,av1.w};         \
        float b[8] = {bv0.x,bv0.y,bv0.z,bv0.w,bv1.x,bv1.y,bv1.z,bv1.w};         \
        _Pragma("unroll")                                                       \
        for (int i = 0; i < 8; i++)                                             \
            _Pragma("unroll")                                                   \
            for (int j = 0; j < 8; j++)                                         \
                acc[i][j] = fmaf(a[i], b[j], acc[i][j]);                        \
    } }

    LOADG(0);
    STORES(0);
    __syncthreads();
    int buf = 0;
    for (int k0 = 16; k0 < K; k0 += 16) {
        LOADG(k0);
        COMPUTE(buf);
        STORES(buf ^ 1);
        __syncthreads();
        buf ^= 1;
    }
    COMPUTE(buf);

#undef LOADG
#undef STORES
#undef COMPUTE

    // threshold in place
    #pragma unroll
    for (int i = 0; i < 8; i++)
        #pragma unroll
        for (int j = 0; j < 8; j++)
            acc[i][j] = thrf(acc[i][j], scale, th);

    // direct tile
    #pragma unroll
    for (int i = 0; i < 8; i++) {
        #pragma unroll
        for (int j = 0; j < 8; j += 4) {
            float4 v = make_float4(acc[i][j], acc[i][j+1], acc[i][j+2], acc[i][j+3]);
            *(float4*)(C + (size_t)(m0 + ry + i) * N + (n0 + rx + j)) = v;
        }
    }
    if (bx > by) {   // mirrored tile
        #pragma unroll
        for (int j = 0; j < 8; j++) {
            #pragma unroll
            for (int i = 0; i < 8; i += 4) {
                float4 v = make_float4(acc[i][j], acc[i+1][j], acc[i+2][j], acc[i+3][j]);
                *(float4*)(C + (size_t)(n0 + rx + j) * N + (m0 + ry + i)) = v;
            }
        }
    }

    if (csPart) {
        __syncthreads();
        float* red = (float*)As;   // 16*128 floats
        // column partials for direct tile (columns n0+rx+jj, rows m0..m0+127)
        #pragma unroll
        for (int jj = 0; jj < 8; jj++) {
            float s = 0.f;
            #pragma unroll
            for (int i = 0; i < 8; i++) s += acc[i][jj];
            red[ty * 128 + rx + jj] = s;
        }
        __syncthreads();
        if (tid < 128) {
            float s = 0.f;
            #pragma unroll
            for (int p = 0; p < 16; p++) s += red[p * 128 + tid];
            csPart[(size_t)by * N + n0 + tid] = s;
        }
        if (bx > by) {
            __syncthreads();
            // mirror tile colsums = row sums of acc (columns m0+ry+ii, rows n0..n0+127)
            #pragma unroll
            for (int ii = 0; ii < 8; ii++) {
                float s = 0.f;
                #pragma unroll
                for (int j = 0; j < 8; j++) s += acc[ii][j];
                red[tx * 128 + ry + ii] = s;
            }
            __syncthreads();
            if (tid < 128) {
                float s = 0.f;
                #pragma unroll
                for (int p = 0; p < 16; p++) s += red[p * 128 + tid];
                csPart[(size_t)bx * N + m0 + tid] = s;
            }
        }
    }
}

// Deterministic ballot-compacted nonzero index list per target row of an adjacency block.
__global__ void build_idx_kernel(const float* __restrict__ adj, int col_off, int NR,
                                 int* __restrict__ idx, int* __restrict__ cnt)
{
    int i = blockIdx.x;
    const float* r = adj + (size_t)i * NALL + col_off;
    int lane = threadIdx.x;
    int count = 0;
    for (int base = 0; base < NR; base += 32) {
        float v = r[base + lane];
        unsigned m = __ballot_sync(0xffffffffu, v != 0.f);
        int pre = __popc(m & ((1u << lane) - 1u));
        if (v != 0.f && (count + pre) < CAP) idx[(size_t)i * CAP + count + pre] = base + lane;
        count += __popc(m);
    }
    if (lane == 0) cnt[i] = min(count, CAP);
}

// out[i, :128] = sum over listed rows of src (exact: adjacency is 0/1)
__global__ void gather_sum_kernel(const float* __restrict__ src, int lds,
                                  const int* __restrict__ idx, const int* __restrict__ cnt,
                                  float* __restrict__ out, int ldo)
{
    int i = blockIdx.y;
    int j = ((blockIdx.x * blockDim.x + threadIdx.x) << 2);
    int c = cnt[i];
    const int* ip = idx + (size_t)i * CAP;
    float4 s = make_float4(0.f, 0.f, 0.f, 0.f);
    for (int t = 0; t < c; t++) {
        float4 v = *(const float4*)(src + (size_t)ip[t] * lds + j);
        s.x += v.x; s.y += v.y; s.z += v.z; s.w += v.w;
    }
    *(float4*)(out + (size_t)i * ldo + j) = s;
}

// out[i, c] = bias[c] + sum over listed rows of src[*,64]
__global__ void gather64b_kernel(const float* __restrict__ src,
                                 const int* __restrict__ idx, const int* __restrict__ cnt,
                                 const float* __restrict__ bias, float* __restrict__ out)
{
    int i = blockIdx.x;
    int c = threadIdx.x;      // 64 threads
    int n = cnt[i];
    const int* ip = idx + (size_t)i * CAP;
    float s = 0.f;
    for (int t = 0; t < n; t++) s += src[(size_t)ip[t] * 64 + c];
    out[(size_t)i * 64 + c] = s + bias[c];
}

// C[M,64] = A[M,K] @ B[K,64] (+bias) (optional relu) — single pass
__global__ void __launch_bounds__(256)
gemm_n64_kernel(const float* __restrict__ A, const float* __restrict__ B,
                const float* __restrict__ bias, float* __restrict__ C,
                int M, int K, int relu)
{
    __shared__ float As[32][64];
    __shared__ float Bs[32][64];
    int tid = threadIdx.x;
    int m0  = blockIdx.x * 64;
    int ar  = tid >> 3;
    int ac  = (tid & 7) << 2;
    int br  = tid >> 4;
    int bc  = (tid & 15) << 2;
    int ty  = tid >> 4, tx = tid & 15;

    float acc[4][4];
    #pragma unroll
    for (int i = 0; i < 4; i++)
        #pragma unroll
        for (int j = 0; j < 4; j++) acc[i][j] = 0.f;

    for (int k0 = 0; k0 < K; k0 += 32) {
        float4 a0 = *(const float4*)(A + (size_t)(m0 + ar)      * K + k0 + ac);
        float4 a1 = *(const float4*)(A + (size_t)(m0 + ar + 32) * K + k0 + ac);
        float4 b0 = *(const float4*)(B + (size_t)(k0 + br)      * 64 + bc);
        float4 b1 = *(const float4*)(B + (size_t)(k0 + br + 16) * 64 + bc);
        __syncthreads();
        As[ac+0][ar]    = a0.x; As[ac+1][ar]    = a0.y; As[ac+2][ar]    = a0.z; As[ac+3][ar]    = a0.w;
        As[ac+0][ar+32] = a1.x; As[ac+1][ar+32] = a1.y; As[ac+2][ar+32] = a1.z; As[ac+3][ar+32] = a1.w;
        *(float4*)&Bs[br][bc]      = b0;
        *(float4*)&Bs[br + 16][bc] = b1;
        __syncthreads();
        #pragma unroll
        for (int k = 0; k < 32; k++) {
            float4 av = *(const float4*)&As[k][ty << 2];
            float4 bv = *(const float4*)&Bs[k][tx << 2];
            float a[4] = {av.x, av.y, av.z, av.w};
            float b[4] = {bv.x, bv.y, bv.z, bv.w};
            #pragma unroll
            for (int i = 0; i < 4; i++)
                #pragma unroll
                for (int j = 0; j < 4; j++)
                    acc[i][j] = fmaf(a[i], b[j], acc[i][j]);
        }
    }
    int r = m0 + (ty << 2), c = tx << 2;
    #pragma unroll
    for (int i = 0; i < 4; i++)
        #pragma unroll
        for (int j = 0; j < 4; j++) {
            float v = acc[i][j] + (bias ? bias[c + j] : 0.f);
            if (relu) v = fmaxf(v, 0.f);
            C[(size_t)(r + i) * 64 + c + j] = v;
        }
}

// split-K variant: grid (M/64, S); each block handles K chunk [s*Kc, s*Kc+Kc)
__global__ void __launch_bounds__(256)
gemm_n64_splitk_kernel(const float* __restrict__ A, const float* __restrict__ B,
                       float* __restrict__ part, int M, int K, int Kc)
{
    __shared__ float As[32][64];
    __shared__ float Bs[32][64];
    int tid = threadIdx.x;
    int m0  = blockIdx.x * 64;
    int s   = blockIdx.y;
    int kb  = s * Kc, ke = kb + Kc;
    int ar  = tid >> 3;
    int ac  = (tid & 7) << 2;
    int br  = tid >> 4;
    int bc  = (tid & 15) << 2;
    int ty  = tid >> 4, tx = tid & 15;

    float acc[4][4];
    #pragma unroll
    for (int i = 0; i < 4; i++)
        #pragma unroll
        for (int j = 0; j < 4; j++) acc[i][j] = 0.f;

    for (int k0 = kb; k0 < ke; k0 += 32) {
        float4 a0 = *(const float4*)(A + (size_t)(m0 + ar)      * K + k0 + ac);
        float4 a1 = *(const float4*)(A + (size_t)(m0 + ar + 32) * K + k0 + ac);
        float4 b0 = *(const float4*)(B + (size_t)(k0 + br)      * 64 + bc);
        float4 b1 = *(const float4*)(B + (size_t)(k0 + br + 16) * 64 + bc);
        __syncthreads();
        As[ac+0][ar]    = a0.x; As[ac+1][ar]    = a0.y; As[ac+2][ar]    = a0.z; As[ac+3][ar]    = a0.w;
        As[ac+0][ar+32] = a1.x; As[ac+1][ar+32] = a1.y; As[ac+2][ar+32] = a1.z; As[ac+3][ar+32] = a1.w;
        *(float4*)&Bs[br][bc]      = b0;
        *(float4*)&Bs[br + 16][bc] = b1;
        __syncthreads();
        #pragma unroll
        for (int k = 0; k < 32; k++) {
            float4 av = *(const float4*)&As[k][ty << 2];
            float4 bv = *(const float4*)&Bs[k][tx << 2];
            float a[4] = {av.x, av.y, av.z, av.w};
            float b[4] = {bv.x, bv.y, bv.z, bv.w};
            #pragma unroll
            for (int i = 0; i < 4; i++)
                #pragma unroll
                for (int j = 0; j < 4; j++)
                    acc[i][j] = fmaf(a[i], b[j], acc[i][j]);
        }
    }
    int r = m0 + (ty << 2), c = tx << 2;
    #pragma unroll
    for (int i = 0; i < 4; i++)
        #pragma unroll
        for (int j = 0; j < 4; j++)
            part[(size_t)s * M * 64 + (size_t)(r + i) * 64 + c + j] = acc[i][j];
}

__global__ void splitk_reduce_kernel(const float* __restrict__ part, const float* __restrict__ bias,
                                     float* __restrict__ C, int M, int S, int relu)
{
    int idx = blockIdx.x * 256 + threadIdx.x;
    if (idx >= M * 64) return;
    float s = 0.f;
    for (int p = 0; p < S; p++) s += part[(size_t)p * M * 64 + idx];
    if (bias) s += bias[idx & 63];
    if (relu) s = fmaxf(s, 0.f);
    C[idx] = s;
}

// CS[m][j] = sum_p CSP[m][p][j]
__global__ void cs_reduce_kernel(const float* __restrict__ CSP, float* __restrict__ CS)
{
    int m = blockIdx.y;
    int j = blockIdx.x * 256 + threadIdx.x;
    float s = 0.f;
    #pragma unroll
    for (int p = 0; p < 32; p++) s += CSP[((size_t)m * 32 + p) * NT + j];
    CS[m * NT + j] = s;
}

// per-column combine coefficients + closed-form colsum of pre (CT0)
__global__ void coefs_kernel(const float* __restrict__ sgw, const float* __restrict__ ffw,
                             const float* __restrict__ f4w,
                             const float* __restrict__ cs, float* __restrict__ coef,
                             float* __restrict__ ct0)
{
    int j = blockIdx.x * 256 + threadIdx.x;
    float m2 = fmaxf(sgw[0], sgw[1]);
    float e0 = expf(sgw[0] - m2), e1 = expf(sgw[1] - m2);
    float sa0 = e0 / (e0 + e1), sa1 = e1 / (e0 + e1);
    float mf = fmaxf(ffw[0], ffw[1]);
    float f0 = expf(ffw[0] - mf), f1 = expf(ffw[1] - mf);
    float fa0 = f0 / (f0 + f1), fa1 = f1 / (f0 + f1);
    float m4 = fmaxf(fmaxf(f4w[0], f4w[1]), fmaxf(f4w[2], f4w[3]));
    float w0 = expf(f4w[0] - m4), w1 = expf(f4w[1] - m4), w2 = expf(f4w[2] - m4), w3 = expf(f4w[3] - m4);
    float ws = w0 + w1 + w2 + w3;
    w0 /= ws; w1 /= ws; w2 /= ws; w3 /= ws;

    float csv[7], cf[7];
    #pragma unroll
    for (int m = 0; m < 7; m++) csv[m] = cs[m * NT + j];
    float uP  = (csv[1] > 0.05f) ? 1.f : 0.f;
    float uQ  = (csv[2] > 0.05f) ? 1.f : 0.f;
    float uFA = (csv[3] > 0.05f) ? 1.f : 0.f;
    float uFS = (csv[4] > 0.05f) ? 1.f : 0.f;
    float uSA = (csv[5] > 0.05f) ? 1.f : 0.f;
    float uSS = (csv[6] > 0.05f) ? 1.f : 0.f;
    float dSem = fmaxf(sa0 * uP  + sa1 * uQ,  1e-12f);
    float dFp  = fmaxf(fa0 * uFA + fa1 * uFS, 1e-12f);
    float dSt  = fmaxf(fa0 * uSA + fa1 * uSS, 1e-12f);

    cf[0] = w0 / fmaxf(csv[0], 1e-12f);
    cf[1] = w1 * sa0 / (fmaxf(csv[1], 1e-12f) * dSem);
    cf[2] = w1 * sa1 / (fmaxf(csv[2], 1e-12f) * dSem);
    cf[3] = w2 * fa0 / (fmaxf(csv[3], 1e-12f) * dFp);
    cf[4] = w2 * fa1 / (fmaxf(csv[4], 1e-12f) * dFp);
    cf[5] = w3 * fa0 / (fmaxf(csv[5], 1e-12f) * dSt);
    cf[6] = w3 * fa1 / (fmaxf(csv[6], 1e-12f) * dSt);

    float c0 = 0.f;
    #pragma unroll
    for (int m = 0; m < 7; m++) { coef[m * NT + j] = cf[m]; c0 += cf[m] * csv[m]; }
    ct0[j] = c0;   // column sum of pre (all entries nonneg)
}

// pre = sum_m coef_m[j] * M_m[i,j]; also emit per-quarter-row sums (for CT)
__global__ void combine_kernel(const float* __restrict__ G,  const float* __restrict__ P,
                               const float* __restrict__ Q,  const float* __restrict__ FA,
                               const float* __restrict__ FS, const float* __restrict__ SA,
                               const float* __restrict__ SS, const float* __restrict__ coef,
                               float* __restrict__ out, float* __restrict__ rowp)
{
    int b = blockIdx.x;
    size_t e = ((size_t)b * 256 + threadIdx.x) << 2;
    int j = (int)(e & (NT - 1));
    float4 r = make_float4(0.f, 0.f, 0.f, 0.f);
#define ACC(buf, m) { float4 v = *(const float4*)((buf) + e);                 \
                      float4 k = *(const float4*)(coef + (m) * NT + j);       \
                      r.x = fmaf(k.x, v.x, r.x); r.y = fmaf(k.y, v.y, r.y);   \
                      r.z = fmaf(k.z, v.z, r.z); r.w = fmaf(k.w, v.w, r.w); }
    ACC(G, 0) ACC(P, 1) ACC(Q, 2) ACC(FA, 3) ACC(FS, 4) ACC(SA, 5) ACC(SS, 6)
#undef ACC
    *(float4*)(out + e) = r;

    float s = r.x + r.y + r.z + r.w;
    #pragma unroll
    for (int o = 16; o; o >>= 1) s += __shfl_xor_sync(0xffffffffu, s, o);
    __shared__ float ws[8];
    int w = threadIdx.x >> 5;
    if ((threadIdx.x & 31) == 0) ws[w] = s;
    __syncthreads();
    if (threadIdx.x == 0) {
        float t = 0.f;
        #pragma unroll
        for (int p = 0; p < 8; p++) t += ws[p];
        rowp[(size_t)(b >> 2) * 4 + (b & 3)] = t;   // 4 quarter-row partials per row
    }
}

__global__ void ct_final_kernel(const float* __restrict__ ct0, const float* __restrict__ rowp,
                                float* __restrict__ ct)
{
    int j = blockIdx.x * 256 + threadIdx.x;
    ct[j] = ct0[j] + rowp[j * 4 + 0] + rowp[j * 4 + 1] + rowp[j * 4 + 2] + rowp[j * 4 + 3];
}

// in-place: A = (A + A^T) / colnorm, paired 32x32 tiles, triangular grid
__global__ void symscale_kernel(float* __restrict__ A, const float* __restrict__ ct)
{
    const int nb = 128;
    int idx = blockIdx.x;
    float nb2 = nb + 0.5f;
    int bi = (int)(nb2 - sqrtf(fmaxf(nb2 * nb2 - 2.0f * idx, 0.f)));
    if (bi < 0) bi = 0;
    if (bi > nb - 1) bi = nb - 1;
    while (bi > 0 && (bi * nb - (bi * (bi - 1)) / 2) > idx) bi--;
    while (((bi + 1) * nb - ((bi + 1) * bi) / 2) <= idx) bi++;
    int bj = bi + (idx - (bi * nb - (bi * (bi - 1)) / 2));

    __shared__ float T1[32][33], T2[32][33];
    int x = threadIdx.x, y0 = threadIdx.y;
    for (int y = y0; y < 32; y += 8) T1[y][x] = A[(size_t)(bi * 32 + y) * NT + bj * 32 + x];
    if (bi != bj)
        for (int y = y0; y < 32; y += 8) T2[y][x] = A[(size_t)(bj * 32 + y) * NT + bi * 32 + x];
    __syncthreads();
    float cj = fmaxf(ct[bj * 32 + x], 1e-12f);
    if (bi == bj) {
        for (int y = y0; y < 32; y += 8)
            A[(size_t)(bi * 32 + y) * NT + bj * 32 + x] = (T1[y][x] + T1[x][y]) / cj;
    } else {
        float ci = fmaxf(ct[bi * 32 + x], 1e-12f);
        for (int y = y0; y < 32; y += 8)
            A[(size_t)(bi * 32 + y) * NT + bj * 32 + x] = (T1[y][x] + T2[x][y]) / cj;
        for (int y = y0; y < 32; y += 8)
            A[(size_t)(bj * 32 + y) * NT + bi * 32 + x] = (T2[y][x] + T1[x][y]) / ci;
    }
}

// H2[i,0:3] = X1[i,:] @ W2
__global__ void x1w2_kernel(const float* __restrict__ X1, const float* __restrict__ W2,
                            float* __restrict__ H2)
{
    int i = blockIdx.x * 256 + threadIdx.x;
    if (i >= NT) return;
    float s0 = 0.f, s1 = 0.f, s2 = 0.f;
    #pragma unroll 8
    for (int k = 0; k < COM; k++) {
        float x = X1[(size_t)i * COM + k];
        s0 = fmaf(x, W2[k * 3 + 0], s0);
        s1 = fmaf(x, W2[k * 3 + 1], s1);
        s2 = fmaf(x, W2[k * 3 + 2], s2);
    }
    H2[i * 3 + 0] = s0; H2[i * 3 + 1] = s1; H2[i * 3 + 2] = s2;
}

// logits row i = log_softmax( NA[i,:] @ H2 + b2 )
__global__ void logits_kernel(const float* __restrict__ A, const float* __restrict__ H2,
                              const float* __restrict__ b2, float* __restrict__ out)
{
    int i = blockIdx.x, tid = threadIdx.x;
    const float* row = A + (size_t)i * NT;
    float s0 = 0.f, s1 = 0.f, s2 = 0.f;
    for (int k = tid; k < NT; k += 256) {
        float a = row[k];
        s0 = fmaf(a, H2[k * 3 + 0], s0);
        s1 = fmaf(a, H2[k * 3 + 1], s1);
        s2 = fmaf(a, H2[k * 3 + 2], s2);
    }
    #pragma unroll
    for (int o = 16; o; o >>= 1) {
        s0 += __shfl_xor_sync(0xffffffffu, s0, o);
        s1 += __shfl_xor_sync(0xffffffffu, s1, o);
        s2 += __shfl_xor_sync(0xffffffffu, s2, o);
    }
    __shared__ float sh[3][8];
    int w = tid >> 5, l = tid & 31;
    if (l == 0) { sh[0][w] = s0; sh[1][w] = s1; sh[2][w] = s2; }
    __syncthreads();
    if (tid == 0) {
        float x0 = 0.f, x1 = 0.f, x2 = 0.f;
        #pragma unroll
        for (int t = 0; t < 8; t++) { x0 += sh[0][t]; x1 += sh[1][t]; x2 += sh[2][t]; }
        x0 += b2[0]; x1 += b2[1]; x2 += b2[2];
        float m  = fmaxf(x0, fmaxf(x1, x2));
        float ls = logf(expf(x0 - m) + expf(x1 - m) + expf(x2 - m));
        out[i * 3 + 0] = x0 - m - ls;
        out[i * 3 + 1] = x1 - m - ls;
        out[i * 3 + 2] = x2 - m - ls;
    }
}

// ---------------- host orchestration ----------------------------------------

extern "C" void kernel_launch(void* const* d_in, const int* in_sizes, int n_in,
                              void* d_out, int out_size)
{
    const float* features  = (const float*)d_in[0];
    const float* adj_ori   = (const float*)d_in[1];
    const float* mp_pap    = (const float*)d_in[2];
    const float* mp_psp    = (const float*)d_in[3];
    // d_in[4]=enc_W, d_in[5]=enc_b : dead in the reference graph
    const float* fgo_w     = (const float*)d_in[6];
    const float* fpo_w     = (const float*)d_in[7];
    const float* sgg_pap_w = (const float*)d_in[8];
    const float* sgg_psp_w = (const float*)d_in[9];
    const float* sg_agg_w  = (const float*)d_in[10];
    const float* f_agg_f_w = (const float*)d_in[11];
    const float* f_agg_w   = (const float*)d_in[12];
    const float* topo_W_a  = (const float*)d_in[13];
    const float* topo_b_a  = (const float*)d_in[14];
    const float* topo_W_s  = (const float*)d_in[15];
    const float* topo_b_s  = (const float*)d_in[16];
    const float* fgt_w_a   = (const float*)d_in[17];
    const float* fgt_w_s   = (const float*)d_in[18];
    const float* gcn_W1    = (const float*)d_in[19];
    const float* gcn_b1    = (const float*)d_in[20];
    const float* gcn_W2    = (const float*)d_in[21];
    const float* gcn_b2    = (const float*)d_in[22];
    (void)in_sizes; (void)n_in; (void)out_size;

    float* out   = (float*)d_out;
    float* NAdj  = out + (size_t)NT * NCLS;   // [4096,4096] new_adj section

    float* big = nullptr; float* sm = nullptr; int* ib = nullptr;
    cudaGetSymbolAddress((void**)&big, g_big);
    cudaGetSymbolAddress((void**)&sm,  g_small);
    cudaGetSymbolAddress((void**)&ib,  g_ibuf);

    float* G   = big + 0ll * NT * NT;
    float* P   = big + 1ll * NT * NT;
    float* Q   = big + 2ll * NT * NT;
    float* FAb = big + 3ll * NT * NT;
    float* FSb = big + 4ll * NT * NT;
    float* SAb = big + 5ll * NT * NT;   // sim_r_A, then s_h_A
    float* SSb = big + 6ll * NT * NT;

    float* XN    = sm + OFF_XN;
    float* SIMS  = sm + OFF_SIMS;
    float* FPA   = sm + OFF_FPA;
    float* FPS   = sm + OFF_FPS;
    float* THA   = sm + OFF_THA;
    float* THS   = sm + OFF_THS;
    float* SWA   = sm + OFF_SWA;
    float* SWS   = sm + OFF_SWS;
    float* H0    = sm + OFF_H0;
    float* X1    = sm + OFF_X1;
    float* H2    = sm + OFF_H2;
    float* CS    = sm + OFF_CS;
    float* COEF  = sm + OFF_COEF;
    float* CT0   = sm + OFF_CT0;
    float* CT    = sm + OFF_CT;
    float* ROWP  = sm + OFF_ROWP;
    float* CSP   = sm + OFF_CSP;
    float* SPART = sm + OFF_SPART;

    int* IDXA = ib + OFF_IDXA; int* CNTA = ib + OFF_CNTA;
    int* IDXS = ib + OFF_IDXS; int* CNTS = ib + OFF_CNTS;

    const int TRI32 = 32 * 33 / 2;   // 528
    const int TRI8  = 8 * 9 / 2;     // 36
    dim3 bSym(32, 8);

    // ---- g_targ / sem_pap / sem_psp ----
    prep_norm_kernel<<<NT / 4, 128>>>(features, fgo_w, XN, NT, FEAT, 2);
    simgemm_kernel<<<TRI32, 256>>>(XN, G, NT, 256, 0.5f, 0.1f, CSP + 0ll * 32 * NT, 32);
    prep_norm_kernel<<<NT / 4, 128>>>(mp_pap, sgg_pap_w, XN, NT, MPD, 2);
    simgemm_kernel<<<TRI32, 256>>>(XN, P, NT, 128, 0.5f, 0.1f, CSP + 1ll * 32 * NT, 32);
    prep_norm_kernel<<<NT / 4, 128>>>(mp_psp, sgg_psp_w, XN, NT, MPD, 2);
    simgemm_kernel<<<TRI32, 256>>>(XN, Q, NT, 128, 0.5f, 0.1f, CSP + 2ll * 32 * NT, 32);

    // ---- relation A ----
    prep_norm_kernel<<<NT / 4, 128>>>(features + (size_t)NT * FEAT, fgo_w, XN, NAr, FEAT, 2);
    simgemm_kernel<<<TRI32, 256>>>(XN, SAb, NAr, 256, 0.5f, 0.1f, nullptr, 32);       // sim_r_A
    build_idx_kernel<<<NT, 32>>>(adj_ori, NT, NAr, IDXA, CNTA);
    // topo_hid_A = ori_g @ (sim_r_A @ W_a) + b_a   (reassociated)
    gemm_n64_splitk_kernel<<<dim3(NT / 64, 8), 256>>>(SAb, topo_W_a, SPART, NT, NAr, NAr / 8);
    splitk_reduce_kernel<<<(NT * 64) / 256, 256>>>(SPART, nullptr, SWA, NT, 8, 0);
    gather64b_kernel<<<NT, 64>>>(SWA, IDXA, CNTA, topo_b_a, THA);
    gather_sum_kernel<<<dim3(1, NT), 32>>>(features + (size_t)NT * FEAT, FEAT, IDXA, CNTA, FPA, FEAT);
    prep_norm_kernel<<<NT / 4, 128>>>(FPA, fpo_w, XN, NT, FEAT, 2);
    simgemm_kernel<<<TRI32, 256>>>(XN, FAb, NT, 256, 0.5f, 0.2f, CSP + 3ll * 32 * NT, 32);  // f_h_A
    prep_norm_kernel<<<NT / 4, 128>>>(THA, fgt_w_a, XN, NT, COM, 2);
    simgemm_kernel<<<TRI32, 256>>>(XN, SAb, NT, 128, 0.5f, 0.1f, CSP + 5ll * 32 * NT, 32);  // s_h_A

    // ---- relation S ----
    prep_norm_kernel<<<NSr / 4, 128>>>(features + (size_t)(NT + NAr) * FEAT, fgo_w, XN, NSr, FEAT, 2);
    simgemm_kernel<<<TRI8, 256>>>(XN, SIMS, NSr, 256, 0.5f, 0.1f, nullptr, 8);        // sim_r_S
    build_idx_kernel<<<NT, 32>>>(adj_ori, NT + NAr, NSr, IDXS, CNTS);
    gemm_n64_splitk_kernel<<<dim3(NSr / 64, 8), 256>>>(SIMS, topo_W_s, SPART, NSr, NSr, NSr / 8);
    splitk_reduce_kernel<<<(NSr * 64) / 256, 256>>>(SPART, nullptr, SWS, NSr, 8, 0);
    gather64b_kernel<<<NT, 64>>>(SWS, IDXS, CNTS, topo_b_s, THS);
    gather_sum_kernel<<<dim3(1, NT), 32>>>(features + (size_t)(NT + NAr) * FEAT, FEAT, IDXS, CNTS, FPS, FEAT);
    prep_norm_kernel<<<NT / 4, 128>>>(FPS, fpo_w, XN, NT, FEAT, 2);
    simgemm_kernel<<<TRI32, 256>>>(XN, FSb, NT, 256, 0.5f, 0.2f, CSP + 4ll * 32 * NT, 32);  // f_h_S
    prep_norm_kernel<<<NT / 4, 128>>>(THS, fgt_w_s, XN, NT, COM, 2);
    simgemm_kernel<<<TRI32, 256>>>(XN, SSb, NT, 128, 0.5f, 0.1f, CSP + 6ll * 32 * NT, 32);  // s_h_S

    // ---- fused channel attention ----
    cs_reduce_kernel<<<dim3(NT / 256, 7), 256>>>(CSP, CS);
    coefs_kernel<<<NT / 256, 256>>>(sg_agg_w, f_agg_f_w, f_agg_w, CS, COEF, CT0);
    combine_kernel<<<(NT * NT) / 1024, 256>>>(G, P, Q, FAb, FSb, SAb, SSb, COEF, NAdj, ROWP);
    ct_final_kernel<<<NT / 256, 256>>>(CT0, ROWP, CT);
    symscale_kernel<<<128 * 129 / 2, bSym>>>(NAdj, CT);

    // ---- GCN ----
    gemm_n64_kernel<<<NT / 64, 256>>>(features, gcn_W1, nullptr, H0, NT, FEAT, 0);
    gemm_n64_splitk_kernel<<<dim3(NT / 64, 8), 256>>>(NAdj, H0, SPART, NT, NT, NT / 8);
    splitk_reduce_kernel<<<(NT * 64) / 256, 256>>>(SPART, gcn_b1, X1, NT, 8, 1);
    x1w2_kernel<<<NT / 256, 256>>>(X1, gcn_W2, H2);
    logits_kernel<<<NT, 256>>>(NAdj, H2, gcn_b2, out);
}

// round 4
// speedup vs baseline: 1.5542x; 1.0022x over previous
#include <cuda_runtime.h>
#include <math.h>

#define NT   4096
#define NAr  4096
#define NSr  1024
#define NALL 9216
#define FEAT 128
#define COM  64
#define MPD  64
#define NCLS 3
#define CAP  128   // max nnz per adjacency row (expected ~20, p=0.005)

// ---------------- static device scratch (no allocations allowed) -------------
__device__ float g_big[7ll * NT * NT];

#define OFF_XN    0                          // 4096*256
#define OFF_SIMS  (OFF_XN   + NT*256)        // 1024*1024
#define OFF_FPA   (OFF_SIMS + NSr*NSr)       // 4096*128
#define OFF_FPS   (OFF_FPA  + NT*FEAT)       // 4096*128
#define OFF_THA   (OFF_FPS  + NT*FEAT)       // 4096*64
#define OFF_THS   (OFF_THA  + NT*COM)        // 4096*64
#define OFF_SWA   (OFF_THS  + NT*COM)        // 4096*64
#define OFF_SWS   (OFF_SWA  + NT*COM)        // 1024*64
#define OFF_H0    (OFF_SWS  + NSr*COM)       // 4096*64
#define OFF_X1    (OFF_H0   + NT*COM)        // 4096*64
#define OFF_H2    (OFF_X1   + NT*COM)        // 4096*3
#define OFF_CS    (OFF_H2   + NT*NCLS)       // 7*4096
#define OFF_COEF  (OFF_CS   + 7*NT)          // 7*4096
#define OFF_CT0   (OFF_COEF + 7*NT)          // 4096
#define OFF_CT    (OFF_CT0  + NT)            // 4096
#define OFF_ROWP  (OFF_CT   + NT)            // 4096*4
#define OFF_CSP   (OFF_ROWP + 4*NT)          // 7*32*4096
#define OFF_SPART (OFF_CSP  + 7*32*NT)       // 8*4096*64
#define SMALL_TOT (OFF_SPART + 8*NT*64)
__device__ float g_small[SMALL_TOT];

#define OFF_IDXA 0
#define OFF_CNTA (OFF_IDXA + NT*CAP)
#define OFF_IDXS (OFF_CNTA + NT)
#define OFF_CNTS (OFF_IDXS + NT*CAP)
#define IBUF_TOT (OFF_CNTS + NT)
__device__ int g_ibuf[IBUF_TOT];

// ---------------- packed f32x2 helpers (bit-identical IEEE fp32 per lane) ----
typedef unsigned long long u64t;

__device__ __forceinline__ u64t bcast2(float a)
{
    u64t r;
    asm("mov.b64 %0, {%1, %1};" : "=l"(r) : "r"(__float_as_uint(a)));
    return r;
}
__device__ __forceinline__ void fma2(u64t& acc, u64t a, u64t b)
{
    asm("fma.rn.f32x2 %0, %1, %2, %0;" : "+l"(acc) : "l"(a), "l"(b));
}
__device__ __forceinline__ float2 unpack2(u64t v)
{
    unsigned int lo, hi;
    asm("mov.b64 {%0, %1}, %2;" : "=r"(lo), "=r"(hi) : "l"(v));
    return make_float2(__uint_as_float(lo), __uint_as_float(hi));
}

// ---------------- kernels ----------------------------------------------------

__global__ void prep_norm_kernel(const float* __restrict__ src, const float* __restrict__ w,
                                 float* __restrict__ dst, int N, int D, int H)
{
    int row  = blockIdx.x * (blockDim.x >> 5) + (threadIdx.x >> 5);
    int lane = threadIdx.x & 31;
    if (row >= N) return;
    int HD = H * D;
    for (int h = 0; h < H; h++) {
        float ss = 0.f;
        for (int d = lane; d < D; d += 32) {
            float v = src[(size_t)row * D + d] * w[h * D + d];
            ss += v * v;
        }
        #pragma unroll
        for (int o = 16; o; o >>= 1) ss += __shfl_xor_sync(0xffffffffu, ss, o);
        float inv = 1.f / fmaxf(sqrtf(ss), 1e-12f);
        for (int d = lane; d < D; d += 32)
            dst[(size_t)row * HD + h * D + d] = src[(size_t)row * D + d] * w[h * D + d] * inv;
    }
}

__device__ __forceinline__ float thrf(float v, float scale, float th)
{
    v *= scale;
    return (v < th) ? 0.f : v;
}

// C = threshold(scale * X @ X^T). Triangular grid, double-buffered smem, f32x2 FMA.
__global__ void __launch_bounds__(256, 2)
simgemm_kernel(const float* __restrict__ X, float* __restrict__ C,
               int N, int K, float scale, float th,
               float* __restrict__ csPart, int nBlk)
{
    int idx = blockIdx.x;
    float nb2 = nBlk + 0.5f;
    int by = (int)(nb2 - sqrtf(fmaxf(nb2 * nb2 - 2.0f * idx, 0.f)));
    if (by < 0) by = 0;
    if (by > nBlk - 1) by = nBlk - 1;
    while (by > 0 && (by * nBlk - (by * (by - 1)) / 2) > idx) by--;
    while (((by + 1) * nBlk - ((by + 1) * by) / 2) <= idx) by++;
    int bx = by + (idx - (by * nBlk - (by * (by - 1)) / 2));

    const int m0 = by * 128, n0 = bx * 128;

    __shared__ float As[2][16][128];
    __shared__ float Bs[2][16][128];

    const int tid = threadIdx.x;
    const int ldr = tid >> 2;
    const int ldc = (tid & 3) << 2;
    const int ty  = tid >> 4;
    const int tx  = tid & 15;
    const int ry  = ty << 3;
    const int rx  = tx << 3;

    u64t acc2[8][4];
    #pragma unroll
    for (int i = 0; i < 8; i++)
        #pragma unroll
        for (int j = 0; j < 4; j++) acc2[i][j] = 0ull;

    float4 a0, a1, b0, b1;

#define LOADG(k0) {                                                             \
    a0 = *(const float4*)(X + (size_t)(m0 + ldr)      * K + (k0) + ldc);        \
    a1 = *(const float4*)(X + (size_t)(m0 + ldr + 64) * K + (k0) + ldc);        \
    b0 = *(const float4*)(X + (size_t)(n0 + ldr)      * K + (k0) + ldc);        \
    b1 = *(const float4*)(X + (size_t)(n0 + ldr + 64) * K + (k0) + ldc); }

#define STORES(bf) {                                                            \
    As[bf][ldc+0][ldr]    = a0.x; As[bf][ldc+1][ldr]    = a0.y;                 \
    As[bf][ldc+2][ldr]    = a0.z; As[bf][ldc+3][ldr]    = a0.w;                 \
    As[bf][ldc+0][ldr+64] = a1.x; As[bf][ldc+1][ldr+64] = a1.y;                 \
    As[bf][ldc+2][ldr+64] = a1.z; As[bf][ldc+3][ldr+64] = a1.w;                 \
    Bs[bf][ldc+0][ldr]    = b0.x; Bs[bf][ldc+1][ldr]    = b0.y;                 \
    Bs[bf][ldc+2][ldr]    = b0.z; Bs[bf][ldc+3][ldr]    = b0.w;                 \
    Bs[bf][ldc+0][ldr+64] = b1.x; Bs[bf][ldc+1][ldr+64] = b1.y;                 \
    Bs[bf][ldc+2][ldr+64] = b1.z; Bs[bf][ldc+3][ldr+64] = b1.w; }

#define COMPUTE(bf) {                                                           \
    _Pragma("unroll")                                                           \
    for (int k = 0; k < 16; k++) {                                              \
        float4 av0 = *(const float4*)&As[bf][k][ry];                            \
        float4 av1 = *(const float4*)&As[bf][k][ry + 4];                        \
        float4 bv0 = *(const float4*)&Bs[bf][k][rx];                            \
        float4 bv1 = *(const float4*)&Bs[bf][k][rx + 4];                        \
        u64t bp[4];                                                             \
        bp[0] = ((const u64t*)&bv0)[0]; bp[1] = ((const u64t*)&bv0)[1];         \
        bp[2] = ((const u64t*)&bv1)[0]; bp[3] = ((const u64t*)&bv1)[1];         \
        float a[8] = {av0.x,av0.y,av0.z,av0.w,av1.x,av1.y,av1.z,av1.w};         \
        _Pragma("unroll")                                                       \
        for (int i = 0; i < 8; i++) {                                           \
            u64t ai = bcast2(a[i]);                                             \
            fma2(acc2[i][0], ai, bp[0]);                                        \
            fma2(acc2[i][1], ai, bp[1]);                                        \
            fma2(acc2[i][2], ai, bp[2]);                                        \
            fma2(acc2[i][3], ai, bp[3]);                                        \
        }                                                                       \
    } }

    LOADG(0);
    STORES(0);
    __syncthreads();
    int buf = 0;
    for (int k0 = 16; k0 < K; k0 += 16) {
        LOADG(k0);
        COMPUTE(buf);
        STORES(buf ^ 1);
        __syncthreads();
        buf ^= 1;
    }
    COMPUTE(buf);

#undef LOADG
#undef STORES
#undef COMPUTE

    // unpack + threshold
    float acc[8][8];
    #pragma unroll
    for (int i = 0; i < 8; i++)
        #pragma unroll
        for (int jp = 0; jp < 4; jp++) {
            float2 v = unpack2(acc2[i][jp]);
            acc[i][2 * jp + 0] = thrf(v.x, scale, th);
            acc[i][2 * jp + 1] = thrf(v.y, scale, th);
        }

    #pragma unroll
    for (int i = 0; i < 8; i++) {
        #pragma unroll
        for (int j = 0; j < 8; j += 4) {
            float4 v = make_float4(acc[i][j], acc[i][j+1], acc[i][j+2], acc[i][j+3]);
            *(float4*)(C + (size_t)(m0 + ry + i) * N + (n0 + rx + j)) = v;
        }
    }
    if (bx > by) {
        #pragma unroll
        for (int j = 0; j < 8; j++) {
            #pragma unroll
            for (int i = 0; i < 8; i += 4) {
                float4 v = make_float4(acc[i][j], acc[i+1][j], acc[i+2][j], acc[i+3][j]);
                *(float4*)(C + (size_t)(n0 + rx + j) * N + (m0 + ry + i)) = v;
            }
        }
    }

    if (csPart) {
        __syncthreads();
        float* red = (float*)As;
        #pragma unroll
        for (int jj = 0; jj < 8; jj++) {
            float s = 0.f;
            #pragma unroll
            for (int i = 0; i < 8; i++) s += acc[i][jj];
            red[ty * 128 + rx + jj] = s;
        }
        __syncthreads();
        if (tid < 128) {
            float s = 0.f;
            #pragma unroll
            for (int p = 0; p < 16; p++) s += red[p * 128 + tid];
            csPart[(size_t)by * N + n0 + tid] = s;
        }
        if (bx > by) {
            __syncthreads();
            #pragma unroll
            for (int ii = 0; ii < 8; ii++) {
                float s = 0.f;
                #pragma unroll
                for (int j = 0; j < 8; j++) s += acc[ii][j];
                red[tx * 128 + ry + ii] = s;
            }
            __syncthreads();
            if (tid < 128) {
                float s = 0.f;
                #pragma unroll
                for (int p = 0; p < 16; p++) s += red[p * 128 + tid];
                csPart[(size_t)bx * N + m0 + tid] = s;
            }
        }
    }
}

// Deterministic ballot-compacted nonzero index list per target row of an adjacency block.
__global__ void build_idx_kernel(const float* __restrict__ adj, int col_off, int NR,
                                 int* __restrict__ idx, int* __restrict__ cnt)
{
    int i = blockIdx.x;
    const float* r = adj + (size_t)i * NALL + col_off;
    int lane = threadIdx.x;
    int count = 0;
    for (int base = 0; base < NR; base += 32) {
        float v = r[base + lane];
        unsigned m = __ballot_sync(0xffffffffu, v != 0.f);
        int pre = __popc(m & ((1u << lane) - 1u));
        if (v != 0.f && (count + pre) < CAP) idx[(size_t)i * CAP + count + pre] = base + lane;
        count += __popc(m);
    }
    if (lane == 0) cnt[i] = min(count, CAP);
}

__global__ void gather_sum_kernel(const float* __restrict__ src, int lds,
                                  const int* __restrict__ idx, const int* __restrict__ cnt,
                                  float* __restrict__ out, int ldo)
{
    int i = blockIdx.y;
    int j = ((blockIdx.x * blockDim.x + threadIdx.x) << 2);
    int c = cnt[i];
    const int* ip = idx + (size_t)i * CAP;
    float4 s = make_float4(0.f, 0.f, 0.f, 0.f);
    for (int t = 0; t < c; t++) {
        float4 v = *(const float4*)(src + (size_t)ip[t] * lds + j);
        s.x += v.x; s.y += v.y; s.z += v.z; s.w += v.w;
    }
    *(float4*)(out + (size_t)i * ldo + j) = s;
}

__global__ void gather64b_kernel(const float* __restrict__ src,
                                 const int* __restrict__ idx, const int* __restrict__ cnt,
                                 const float* __restrict__ bias, float* __restrict__ out)
{
    int i = blockIdx.x;
    int c = threadIdx.x;
    int n = cnt[i];
    const int* ip = idx + (size_t)i * CAP;
    float s = 0.f;
    for (int t = 0; t < n; t++) s += src[(size_t)ip[t] * 64 + c];
    out[(size_t)i * 64 + c] = s + bias[c];
}

// C[M,64] = A[M,K] @ B[K,64] (+bias) (optional relu) — f32x2 inner
__global__ void __launch_bounds__(256)
gemm_n64_kernel(const float* __restrict__ A, const float* __restrict__ B,
                const float* __restrict__ bias, float* __restrict__ C,
                int M, int K, int relu)
{
    __shared__ float As[32][64];
    __shared__ float Bs[32][64];
    int tid = threadIdx.x;
    int m0  = blockIdx.x * 64;
    int ar  = tid >> 3;
    int ac  = (tid & 7) << 2;
    int br  = tid >> 4;
    int bc  = (tid & 15) << 2;
    int ty  = tid >> 4, tx = tid & 15;

    u64t acc2[4][2];
    #pragma unroll
    for (int i = 0; i < 4; i++) { acc2[i][0] = 0ull; acc2[i][1] = 0ull; }

    for (int k0 = 0; k0 < K; k0 += 32) {
        float4 a0 = *(const float4*)(A + (size_t)(m0 + ar)      * K + k0 + ac);
        float4 a1 = *(const float4*)(A + (size_t)(m0 + ar + 32) * K + k0 + ac);
        float4 b0 = *(const float4*)(B + (size_t)(k0 + br)      * 64 + bc);
        float4 b1 = *(const float4*)(B + (size_t)(k0 + br + 16) * 64 + bc);
        __syncthreads();
        As[ac+0][ar]    = a0.x; As[ac+1][ar]    = a0.y; As[ac+2][ar]    = a0.z; As[ac+3][ar]    = a0.w;
        As[ac+0][ar+32] = a1.x; As[ac+1][ar+32] = a1.y; As[ac+2][ar+32] = a1.z; As[ac+3][ar+32] = a1.w;
        *(float4*)&Bs[br][bc]      = b0;
        *(float4*)&Bs[br + 16][bc] = b1;
        __syncthreads();
        #pragma unroll
        for (int k = 0; k < 32; k++) {
            float4 av = *(const float4*)&As[k][ty << 2];
            float4 bv = *(const float4*)&Bs[k][tx << 2];
            u64t bp0 = ((const u64t*)&bv)[0], bp1 = ((const u64t*)&bv)[1];
            float a[4] = {av.x, av.y, av.z, av.w};
            #pragma unroll
            for (int i = 0; i < 4; i++) {
                u64t ai = bcast2(a[i]);
                fma2(acc2[i][0], ai, bp0);
                fma2(acc2[i][1], ai, bp1);
            }
        }
    }
    int r = m0 + (ty << 2), c = tx << 2;
    #pragma unroll
    for (int i = 0; i < 4; i++) {
        float2 v0 = unpack2(acc2[i][0]);
        float2 v1 = unpack2(acc2[i][1]);
        float vv[4] = {v0.x, v0.y, v1.x, v1.y};
        #pragma unroll
        for (int j = 0; j < 4; j++) {
            float v = vv[j] + (bias ? bias[c + j] : 0.f);
            if (relu) v = fmaxf(v, 0.f);
            C[(size_t)(r + i) * 64 + c + j] = v;
        }
    }
}

// split-K variant: grid (M/64, S)
__global__ void __launch_bounds__(256)
gemm_n64_splitk_kernel(const float* __restrict__ A, const float* __restrict__ B,
                       float* __restrict__ part, int M, int K, int Kc)
{
    __shared__ float As[32][64];
    __shared__ float Bs[32][64];
    int tid = threadIdx.x;
    int m0  = blockIdx.x * 64;
    int s   = blockIdx.y;
    int kb  = s * Kc, ke = kb + Kc;
    int ar  = tid >> 3;
    int ac  = (tid & 7) << 2;
    int br  = tid >> 4;
    int bc  = (tid & 15) << 2;
    int ty  = tid >> 4, tx = tid & 15;

    u64t acc2[4][2];
    #pragma unroll
    for (int i = 0; i < 4; i++) { acc2[i][0] = 0ull; acc2[i][1] = 0ull; }

    for (int k0 = kb; k0 < ke; k0 += 32) {
        float4 a0 = *(const float4*)(A + (size_t)(m0 + ar)      * K + k0 + ac);
        float4 a1 = *(const float4*)(A + (size_t)(m0 + ar + 32) * K + k0 + ac);
        float4 b0 = *(const float4*)(B + (size_t)(k0 + br)      * 64 + bc);
        float4 b1 = *(const float4*)(B + (size_t)(k0 + br + 16) * 64 + bc);
        __syncthreads();
        As[ac+0][ar]    = a0.x; As[ac+1][ar]    = a0.y; As[ac+2][ar]    = a0.z; As[ac+3][ar]    = a0.w;
        As[ac+0][ar+32] = a1.x; As[ac+1][ar+32] = a1.y; As[ac+2][ar+32] = a1.z; As[ac+3][ar+32] = a1.w;
        *(float4*)&Bs[br][bc]      = b0;
        *(float4*)&Bs[br + 16][bc] = b1;
        __syncthreads();
        #pragma unroll
        for (int k = 0; k < 32; k++) {
            float4 av = *(const float4*)&As[k][ty << 2];
            float4 bv = *(const float4*)&Bs[k][tx << 2];
            u64t bp0 = ((const u64t*)&bv)[0], bp1 = ((const u64t*)&bv)[1];
            float a[4] = {av.x, av.y, av.z, av.w};
            #pragma unroll
            for (int i = 0; i < 4; i++) {
                u64t ai = bcast2(a[i]);
                fma2(acc2[i][0], ai, bp0);
                fma2(acc2[i][1], ai, bp1);
            }
        }
    }
    int r = m0 + (ty << 2), c = tx << 2;
    #pragma unroll
    for (int i = 0; i < 4; i++) {
        float2 v0 = unpack2(acc2[i][0]);
        float2 v1 = unpack2(acc2[i][1]);
        float vv[4] = {v0.x, v0.y, v1.x, v1.y};
        #pragma unroll
        for (int j = 0; j < 4; j++)
            part[(size_t)s * M * 64 + (size_t)(r + i) * 64 + c + j] = vv[j];
    }
}

__global__ void splitk_reduce_kernel(const float* __restrict__ part, const float* __restrict__ bias,
                                     float* __restrict__ C, int M, int S, int relu)
{
    int idx = blockIdx.x * 256 + threadIdx.x;
    if (idx >= M * 64) return;
    float s = 0.f;
    for (int p = 0; p < S; p++) s += part[(size_t)p * M * 64 + idx];
    if (bias) s += bias[idx & 63];
    if (relu) s = fmaxf(s, 0.f);
    C[idx] = s;
}

__global__ void cs_reduce_kernel(const float* __restrict__ CSP, float* __restrict__ CS)
{
    int m = blockIdx.y;
    int j = blockIdx.x * 256 + threadIdx.x;
    float s = 0.f;
    #pragma unroll
    for (int p = 0; p < 32; p++) s += CSP[((size_t)m * 32 + p) * NT + j];
    CS[m * NT + j] = s;
}

__global__ void coefs_kernel(const float* __restrict__ sgw, const float* __restrict__ ffw,
                             const float* __restrict__ f4w,
                             const float* __restrict__ cs, float* __restrict__ coef,
                             float* __restrict__ ct0)
{
    int j = blockIdx.x * 256 + threadIdx.x;
    float m2 = fmaxf(sgw[0], sgw[1]);
    float e0 = expf(sgw[0] - m2), e1 = expf(sgw[1] - m2);
    float sa0 = e0 / (e0 + e1), sa1 = e1 / (e0 + e1);
    float mf = fmaxf(ffw[0], ffw[1]);
    float f0 = expf(ffw[0] - mf), f1 = expf(ffw[1] - mf);
    float fa0 = f0 / (f0 + f1), fa1 = f1 / (f0 + f1);
    float m4 = fmaxf(fmaxf(f4w[0], f4w[1]), fmaxf(f4w[2], f4w[3]));
    float w0 = expf(f4w[0] - m4), w1 = expf(f4w[1] - m4), w2 = expf(f4w[2] - m4), w3 = expf(f4w[3] - m4);
    float ws = w0 + w1 + w2 + w3;
    w0 /= ws; w1 /= ws; w2 /= ws; w3 /= ws;

    float csv[7], cf[7];
    #pragma unroll
    for (int m = 0; m < 7; m++) csv[m] = cs[m * NT + j];
    float uP  = (csv[1] > 0.05f) ? 1.f : 0.f;
    float uQ  = (csv[2] > 0.05f) ? 1.f : 0.f;
    float uFA = (csv[3] > 0.05f) ? 1.f : 0.f;
    float uFS = (csv[4] > 0.05f) ? 1.f : 0.f;
    float uSA = (csv[5] > 0.05f) ? 1.f : 0.f;
    float uSS = (csv[6] > 0.05f) ? 1.f : 0.f;
    float dSem = fmaxf(sa0 * uP  + sa1 * uQ,  1e-12f);
    float dFp  = fmaxf(fa0 * uFA + fa1 * uFS, 1e-12f);
    float dSt  = fmaxf(fa0 * uSA + fa1 * uSS, 1e-12f);

    cf[0] = w0 / fmaxf(csv[0], 1e-12f);
    cf[1] = w1 * sa0 / (fmaxf(csv[1], 1e-12f) * dSem);
    cf[2] = w1 * sa1 / (fmaxf(csv[2], 1e-12f) * dSem);
    cf[3] = w2 * fa0 / (fmaxf(csv[3], 1e-12f) * dFp);
    cf[4] = w2 * fa1 / (fmaxf(csv[4], 1e-12f) * dFp);
    cf[5] = w3 * fa0 / (fmaxf(csv[5], 1e-12f) * dSt);
    cf[6] = w3 * fa1 / (fmaxf(csv[6], 1e-12f) * dSt);

    float c0 = 0.f;
    #pragma unroll
    for (int m = 0; m < 7; m++) { coef[m * NT + j] = cf[m]; c0 += cf[m] * csv[m]; }
    ct0[j] = c0;
}

__global__ void combine_kernel(const float* __restrict__ G,  const float* __restrict__ P,
                               const float* __restrict__ Q,  const float* __restrict__ FA,
                               const float* __restrict__ FS, const float* __restrict__ SA,
                               const float* __restrict__ SS, const float* __restrict__ coef,
                               float* __restrict__ out, float* __restrict__ rowp)
{
    int b = blockIdx.x;
    size_t e = ((size_t)b * 256 + threadIdx.x) << 2;
    int j = (int)(e & (NT - 1));
    float4 r = make_float4(0.f, 0.f, 0.f, 0.f);
#define ACC(buf, m) { float4 v = *(const float4*)((buf) + e);                 \
                      float4 k = *(const float4*)(coef + (m) * NT + j);       \
                      r.x = fmaf(k.x, v.x, r.x); r.y = fmaf(k.y, v.y, r.y);   \
                      r.z = fmaf(k.z, v.z, r.z); r.w = fmaf(k.w, v.w, r.w); }
    ACC(G, 0) ACC(P, 1) ACC(Q, 2) ACC(FA, 3) ACC(FS, 4) ACC(SA, 5) ACC(SS, 6)
#undef ACC
    *(float4*)(out + e) = r;

    float s = r.x + r.y + r.z + r.w;
    #pragma unroll
    for (int o = 16; o; o >>= 1) s += __shfl_xor_sync(0xffffffffu, s, o);
    __shared__ float ws[8];
    int w = threadIdx.x >> 5;
    if ((threadIdx.x & 31) == 0) ws[w] = s;
    __syncthreads();
    if (threadIdx.x == 0) {
        float t = 0.f;
        #pragma unroll
        for (int p = 0; p < 8; p++) t += ws[p];
        rowp[(size_t)(b >> 2) * 4 + (b & 3)] = t;
    }
}

__global__ void ct_final_kernel(const float* __restrict__ ct0, const float* __restrict__ rowp,
                                float* __restrict__ ct)
{
    int j = blockIdx.x * 256 + threadIdx.x;
    ct[j] = ct0[j] + rowp[j * 4 + 0] + rowp[j * 4 + 1] + rowp[j * 4 + 2] + rowp[j * 4 + 3];
}

__global__ void symscale_kernel(float* __restrict__ A, const float* __restrict__ ct)
{
    const int nb = 128;
    int idx = blockIdx.x;
    float nb2 = nb + 0.5f;
    int bi = (int)(nb2 - sqrtf(fmaxf(nb2 * nb2 - 2.0f * idx, 0.f)));
    if (bi < 0) bi = 0;
    if (bi > nb - 1) bi = nb - 1;
    while (bi > 0 && (bi * nb - (bi * (bi - 1)) / 2) > idx) bi--;
    while (((bi + 1) * nb - ((bi + 1) * bi) / 2) <= idx) bi++;
    int bj = bi + (idx - (bi * nb - (bi * (bi - 1)) / 2));

    __shared__ float T1[32][33], T2[32][33];
    int x = threadIdx.x, y0 = threadIdx.y;
    for (int y = y0; y < 32; y += 8) T1[y][x] = A[(size_t)(bi * 32 + y) * NT + bj * 32 + x];
    if (bi != bj)
        for (int y = y0; y < 32; y += 8) T2[y][x] = A[(size_t)(bj * 32 + y) * NT + bi * 32 + x];
    __syncthreads();
    float cj = fmaxf(ct[bj * 32 + x], 1e-12f);
    if (bi == bj) {
        for (int y = y0; y < 32; y += 8)
            A[(size_t)(bi * 32 + y) * NT + bj * 32 + x] = (T1[y][x] + T1[x][y]) / cj;
    } else {
        float ci = fmaxf(ct[bi * 32 + x], 1e-12f);
        for (int y = y0; y < 32; y += 8)
            A[(size_t)(bi * 32 + y) * NT + bj * 32 + x] = (T1[y][x] + T2[x][y]) / cj;
        for (int y = y0; y < 32; y += 8)
            A[(size_t)(bj * 32 + y) * NT + bi * 32 + x] = (T2[y][x] + T1[x][y]) / ci;
    }
}

__global__ void x1w2_kernel(const float* __restrict__ X1, const float* __restrict__ W2,
                            float* __restrict__ H2)
{
    int i = blockIdx.x * 256 + threadIdx.x;
    if (i >= NT) return;
    float s0 = 0.f, s1 = 0.f, s2 = 0.f;
    #pragma unroll 8
    for (int k = 0; k < COM; k++) {
        float x = X1[(size_t)i * COM + k];
        s0 = fmaf(x, W2[k * 3 + 0], s0);
        s1 = fmaf(x, W2[k * 3 + 1], s1);
        s2 = fmaf(x, W2[k * 3 + 2], s2);
    }
    H2[i * 3 + 0] = s0; H2[i * 3 + 1] = s1; H2[i * 3 + 2] = s2;
}

__global__ void logits_kernel(const float* __restrict__ A, const float* __restrict__ H2,
                              const float* __restrict__ b2, float* __restrict__ out)
{
    int i = blockIdx.x, tid = threadIdx.x;
    const float* row = A + (size_t)i * NT;
    float s0 = 0.f, s1 = 0.f, s2 = 0.f;
    for (int k = tid; k < NT; k += 256) {
        float a = row[k];
        s0 = fmaf(a, H2[k * 3 + 0], s0);
        s1 = fmaf(a, H2[k * 3 + 1], s1);
        s2 = fmaf(a, H2[k * 3 + 2], s2);
    }
    #pragma unroll
    for (int o = 16; o; o >>= 1) {
        s0 += __shfl_xor_sync(0xffffffffu, s0, o);
        s1 += __shfl_xor_sync(0xffffffffu, s1, o);
        s2 += __shfl_xor_sync(0xffffffffu, s2, o);
    }
    __shared__ float sh[3][8];
    int w = tid >> 5, l = tid & 31;
    if (l == 0) { sh[0][w] = s0; sh[1][w] = s1; sh[2][w] = s2; }
    __syncthreads();
    if (tid == 0) {
        float x0 = 0.f, x1 = 0.f, x2 = 0.f;
        #pragma unroll
        for (int t = 0; t < 8; t++) { x0 += sh[0][t]; x1 += sh[1][t]; x2 += sh[2][t]; }
        x0 += b2[0]; x1 += b2[1]; x2 += b2[2];
        float m  = fmaxf(x0, fmaxf(x1, x2));
        float ls = logf(expf(x0 - m) + expf(x1 - m) + expf(x2 - m));
        out[i * 3 + 0] = x0 - m - ls;
        out[i * 3 + 1] = x1 - m - ls;
        out[i * 3 + 2] = x2 - m - ls;
    }
}

// ---------------- host orchestration ----------------------------------------

extern "C" void kernel_launch(void* const* d_in, const int* in_sizes, int n_in,
                              void* d_out, int out_size)
{
    const float* features  = (const float*)d_in[0];
    const float* adj_ori   = (const float*)d_in[1];
    const float* mp_pap    = (const float*)d_in[2];
    const float* mp_psp    = (const float*)d_in[3];
    const float* fgo_w     = (const float*)d_in[6];
    const float* fpo_w     = (const float*)d_in[7];
    const float* sgg_pap_w = (const float*)d_in[8];
    const float* sgg_psp_w = (const float*)d_in[9];
    const float* sg_agg_w  = (const float*)d_in[10];
    const float* f_agg_f_w = (const float*)d_in[11];
    const float* f_agg_w   = (const float*)d_in[12];
    const float* topo_W_a  = (const float*)d_in[13];
    const float* topo_b_a  = (const float*)d_in[14];
    const float* topo_W_s  = (const float*)d_in[15];
    const float* topo_b_s  = (const float*)d_in[16];
    const float* fgt_w_a   = (const float*)d_in[17];
    const float* fgt_w_s   = (const float*)d_in[18];
    const float* gcn_W1    = (const float*)d_in[19];
    const float* gcn_b1    = (const float*)d_in[20];
    const float* gcn_W2    = (const float*)d_in[21];
    const float* gcn_b2    = (const float*)d_in[22];
    (void)in_sizes; (void)n_in; (void)out_size;

    float* out   = (float*)d_out;
    float* NAdj  = out + (size_t)NT * NCLS;

    float* big = nullptr; float* sm = nullptr; int* ib = nullptr;
    cudaGetSymbolAddress((void**)&big, g_big);
    cudaGetSymbolAddress((void**)&sm,  g_small);
    cudaGetSymbolAddress((void**)&ib,  g_ibuf);

    float* G   = big + 0ll * NT * NT;
    float* P   = big + 1ll * NT * NT;
    float* Q   = big + 2ll * NT * NT;
    float* FAb = big + 3ll * NT * NT;
    float* FSb = big + 4ll * NT * NT;
    float* SAb = big + 5ll * NT * NT;
    float* SSb = big + 6ll * NT * NT;

    float* XN    = sm + OFF_XN;
    float* SIMS  = sm + OFF_SIMS;
    float* FPA   = sm + OFF_FPA;
    float* FPS   = sm + OFF_FPS;
    float* THA   = sm + OFF_THA;
    float* THS   = sm + OFF_THS;
    float* SWA   = sm + OFF_SWA;
    float* SWS   = sm + OFF_SWS;
    float* H0    = sm + OFF_H0;
    float* X1    = sm + OFF_X1;
    float* H2    = sm + OFF_H2;
    float* CS    = sm + OFF_CS;
    float* COEF  = sm + OFF_COEF;
    float* CT0   = sm + OFF_CT0;
    float* CT    = sm + OFF_CT;
    float* ROWP  = sm + OFF_ROWP;
    float* CSP   = sm + OFF_CSP;
    float* SPART = sm + OFF_SPART;

    int* IDXA = ib + OFF_IDXA; int* CNTA = ib + OFF_CNTA;
    int* IDXS = ib + OFF_IDXS; int* CNTS = ib + OFF_CNTS;

    const int TRI32 = 32 * 33 / 2;
    const int TRI8  = 8 * 9 / 2;
    dim3 bSym(32, 8);

    // ---- g_targ / sem_pap / sem_psp ----
    prep_norm_kernel<<<NT / 4, 128>>>(features, fgo_w, XN, NT, FEAT, 2);
    simgemm_kernel<<<TRI32, 256>>>(XN, G, NT, 256, 0.5f, 0.1f, CSP + 0ll * 32 * NT, 32);
    prep_norm_kernel<<<NT / 4, 128>>>(mp_pap, sgg_pap_w, XN, NT, MPD, 2);
    simgemm_kernel<<<TRI32, 256>>>(XN, P, NT, 128, 0.5f, 0.1f, CSP + 1ll * 32 * NT, 32);
    prep_norm_kernel<<<NT / 4, 128>>>(mp_psp, sgg_psp_w, XN, NT, MPD, 2);
    simgemm_kernel<<<TRI32, 256>>>(XN, Q, NT, 128, 0.5f, 0.1f, CSP + 2ll * 32 * NT, 32);

    // ---- relation A ----
    prep_norm_kernel<<<NT / 4, 128>>>(features + (size_t)NT * FEAT, fgo_w, XN, NAr, FEAT, 2);
    simgemm_kernel<<<TRI32, 256>>>(XN, SAb, NAr, 256, 0.5f, 0.1f, nullptr, 32);
    build_idx_kernel<<<NT, 32>>>(adj_ori, NT, NAr, IDXA, CNTA);
    gemm_n64_splitk_kernel<<<dim3(NT / 64, 8), 256>>>(SAb, topo_W_a, SPART, NT, NAr, NAr / 8);
    splitk_reduce_kernel<<<(NT * 64) / 256, 256>>>(SPART, nullptr, SWA, NT, 8, 0);
    gather64b_kernel<<<NT, 64>>>(SWA, IDXA, CNTA, topo_b_a, THA);
    gather_sum_kernel<<<dim3(1, NT), 32>>>(features + (size_t)NT * FEAT, FEAT, IDXA, CNTA, FPA, FEAT);
    prep_norm_kernel<<<NT / 4, 128>>>(FPA, fpo_w, XN, NT, FEAT, 2);
    simgemm_kernel<<<TRI32, 256>>>(XN, FAb, NT, 256, 0.5f, 0.2f, CSP + 3ll * 32 * NT, 32);
    prep_norm_kernel<<<NT / 4, 128>>>(THA, fgt_w_a, XN, NT, COM, 2);
    simgemm_kernel<<<TRI32, 256>>>(XN, SAb, NT, 128, 0.5f, 0.1f, CSP + 5ll * 32 * NT, 32);

    // ---- relation S ----
    prep_norm_kernel<<<NSr / 4, 128>>>(features + (size_t)(NT + NAr) * FEAT, fgo_w, XN, NSr, FEAT, 2);
    simgemm_kernel<<<TRI8, 256>>>(XN, SIMS, NSr, 256, 0.5f, 0.1f, nullptr, 8);
    build_idx_kernel<<<NT, 32>>>(adj_ori, NT + NAr, NSr, IDXS, CNTS);
    gemm_n64_splitk_kernel<<<dim3(NSr / 64, 8), 256>>>(SIMS, topo_W_s, SPART, NSr, NSr, NSr / 8);
    splitk_reduce_kernel<<<(NSr * 64) / 256, 256>>>(SPART, nullptr, SWS, NSr, 8, 0);
    gather64b_kernel<<<NT, 64>>>(SWS, IDXS, CNTS, topo_b_s, THS);
    gather_sum_kernel<<<dim3(1, NT), 32>>>(features + (size_t)(NT + NAr) * FEAT, FEAT, IDXS, CNTS, FPS, FEAT);
    prep_norm_kernel<<<NT / 4, 128>>>(FPS, fpo_w, XN, NT, FEAT, 2);
    simgemm_kernel<<<TRI32, 256>>>(XN, FSb, NT, 256, 0.5f, 0.2f, CSP + 4ll * 32 * NT, 32);
    prep_norm_kernel<<<NT / 4, 128>>>(THS, fgt_w_s, XN, NT, COM, 2);
    simgemm_kernel<<<TRI32, 256>>>(XN, SSb, NT, 128, 0.5f, 0.1f, CSP + 6ll * 32 * NT, 32);

    // ---- fused channel attention ----
    cs_reduce_kernel<<<dim3(NT / 256, 7), 256>>>(CSP, CS);
    coefs_kernel<<<NT / 256, 256>>>(sg_agg_w, f_agg_f_w, f_agg_w, CS, COEF, CT0);
    combine_kernel<<<(NT * NT) / 1024, 256>>>(G, P, Q, FAb, FSb, SAb, SSb, COEF, NAdj, ROWP);
    ct_final_kernel<<<NT / 256, 256>>>(CT0, ROWP, CT);
    symscale_kernel<<<128 * 129 / 2, bSym>>>(NAdj, CT);

    // ---- GCN ----
    gemm_n64_kernel<<<NT / 64, 256>>>(features, gcn_W1, nullptr, H0, NT, FEAT, 0);
    gemm_n64_splitk_kernel<<<dim3(NT / 64, 8), 256>>>(NAdj, H0, SPART, NT, NT, NT / 8);
    splitk_reduce_kernel<<<(NT * 64) / 256, 256>>>(SPART, gcn_b1, X1, NT, 8, 1);
    x1w2_kernel<<<NT / 256, 256>>>(X1, gcn_W2, H2);
    logits_kernel<<<NT, 256>>>(NAdj, H2, gcn_b2, out);
}

// round 5
// speedup vs baseline: 1.5593x; 1.0033x over previous
#include <cuda_runtime.h>
#include <math.h>

#define NT   4096
#define NAr  4096
#define NSr  1024
#define NALL 9216
#define FEAT 128
#define COM  64
#define MPD  64
#define NCLS 3
#define CAP  128   // max nnz per adjacency row (expected ~20, p=0.005)

// ---------------- static device scratch (no allocations allowed) -------------
__device__ float g_big[7ll * NT * NT];

#define OFF_XN    0                          // 4096*256
#define OFF_SIMS  (OFF_XN   + NT*256)        // 1024*1024
#define OFF_FPA   (OFF_SIMS + NSr*NSr)       // 4096*128
#define OFF_FPS   (OFF_FPA  + NT*FEAT)       // 4096*128
#define OFF_THA   (OFF_FPS  + NT*FEAT)       // 4096*64
#define OFF_THS   (OFF_THA  + NT*COM)        // 4096*64
#define OFF_SWA   (OFF_THS  + NT*COM)        // 4096*64
#define OFF_SWS   (OFF_SWA  + NT*COM)        // 1024*64
#define OFF_H0    (OFF_SWS  + NSr*COM)       // 4096*64
#define OFF_X1    (OFF_H0   + NT*COM)        // 4096*64
#define OFF_H2    (OFF_X1   + NT*COM)        // 4096*3
#define OFF_CS    (OFF_H2   + NT*NCLS)       // 7*4096
#define OFF_COEF  (OFF_CS   + 7*NT)          // 7*4096
#define OFF_CT0   (OFF_COEF + 7*NT)          // 4096
#define OFF_CT    (OFF_CT0  + NT)            // 4096
#define OFF_ROWP  (OFF_CT   + NT)            // 4096*4
#define OFF_CSP   (OFF_ROWP + 4*NT)          // 7*32*4096
#define OFF_SPART (OFF_CSP  + 7*32*NT)       // 8*4096*64
#define SMALL_TOT (OFF_SPART + 8*NT*64)
__device__ float g_small[SMALL_TOT];

#define OFF_IDXA 0
#define OFF_CNTA (OFF_IDXA + NT*CAP)
#define OFF_IDXS (OFF_CNTA + NT)
#define OFF_CNTS (OFF_IDXS + NT*CAP)
#define IBUF_TOT (OFF_CNTS + NT)
__device__ int g_ibuf[IBUF_TOT];

// ---------------- packed f32x2 helpers (bit-identical IEEE fp32 per lane) ----
typedef unsigned long long u64t;

__device__ __forceinline__ u64t bcast2(float a)
{
    u64t r;
    asm("mov.b64 %0, {%1, %1};" : "=l"(r) : "r"(__float_as_uint(a)));
    return r;
}
__device__ __forceinline__ void fma2(u64t& acc, u64t a, u64t b)
{
    asm("fma.rn.f32x2 %0, %1, %2, %0;" : "+l"(acc) : "l"(a), "l"(b));
}
__device__ __forceinline__ float2 unpack2(u64t v)
{
    unsigned int lo, hi;
    asm("mov.b64 {%0, %1}, %2;" : "=r"(lo), "=r"(hi) : "l"(v));
    return make_float2(__uint_as_float(lo), __uint_as_float(hi));
}

// ---------------- kernels ----------------------------------------------------

__global__ void prep_norm_kernel(const float* __restrict__ src, const float* __restrict__ w,
                                 float* __restrict__ dst, int N, int D, int H)
{
    int row  = blockIdx.x * (blockDim.x >> 5) + (threadIdx.x >> 5);
    int lane = threadIdx.x & 31;
    if (row >= N) return;
    int HD = H * D;
    for (int h = 0; h < H; h++) {
        float ss = 0.f;
        for (int d = lane; d < D; d += 32) {
            float v = src[(size_t)row * D + d] * w[h * D + d];
            ss += v * v;
        }
        #pragma unroll
        for (int o = 16; o; o >>= 1) ss += __shfl_xor_sync(0xffffffffu, ss, o);
        float inv = 1.f / fmaxf(sqrtf(ss), 1e-12f);
        for (int d = lane; d < D; d += 32)
            dst[(size_t)row * HD + h * D + d] = src[(size_t)row * D + d] * w[h * D + d] * inv;
    }
}

__device__ __forceinline__ float thrf(float v, float scale, float th)
{
    v *= scale;
    return (v < th) ? 0.f : v;
}

// C = threshold(scale * X @ X^T). Triangular grid, double-buffered smem, f32x2 FMA.
// Warp maps to a 4x8 (ty x tx) patch: A-frag 4 distinct addrs/warp, B-frag 8 ->
// 4 smem wavefronts per warp per k (was 6 with the 2x16 map).
__global__ void __launch_bounds__(256, 2)
simgemm_kernel(const float* __restrict__ X, float* __restrict__ C,
               int N, int K, float scale, float th,
               float* __restrict__ csPart, int nBlk)
{
    int idx = blockIdx.x;
    float nb2 = nBlk + 0.5f;
    int by = (int)(nb2 - sqrtf(fmaxf(nb2 * nb2 - 2.0f * idx, 0.f)));
    if (by < 0) by = 0;
    if (by > nBlk - 1) by = nBlk - 1;
    while (by > 0 && (by * nBlk - (by * (by - 1)) / 2) > idx) by--;
    while (((by + 1) * nBlk - ((by + 1) * by) / 2) <= idx) by++;
    int bx = by + (idx - (by * nBlk - (by * (by - 1)) / 2));

    const int m0 = by * 128, n0 = bx * 128;

    __shared__ float As[2][16][128];
    __shared__ float Bs[2][16][128];

    const int tid = threadIdx.x;
    const int ldr = tid >> 2;
    const int ldc = (tid & 3) << 2;
    // 4x8 warp patch map (bijective over 16x16)
    const int wrp = tid >> 5;
    const int ln  = tid & 31;
    const int ty  = ((wrp >> 1) << 2) | (ln >> 3);   // 0..15
    const int tx  = ((wrp & 1) << 3) | (ln & 7);     // 0..15
    const int ry  = ty << 3;
    const int rx  = tx << 3;

    u64t acc2[8][4];
    #pragma unroll
    for (int i = 0; i < 8; i++)
        #pragma unroll
        for (int j = 0; j < 4; j++) acc2[i][j] = 0ull;

    float4 a0, a1, b0, b1;

#define LOADG(k0) {                                                             \
    a0 = *(const float4*)(X + (size_t)(m0 + ldr)      * K + (k0) + ldc);        \
    a1 = *(const float4*)(X + (size_t)(m0 + ldr + 64) * K + (k0) + ldc);        \
    b0 = *(const float4*)(X + (size_t)(n0 + ldr)      * K + (k0) + ldc);        \
    b1 = *(const float4*)(X + (size_t)(n0 + ldr + 64) * K + (k0) + ldc); }

#define STORES(bf) {                                                            \
    As[bf][ldc+0][ldr]    = a0.x; As[bf][ldc+1][ldr]    = a0.y;                 \
    As[bf][ldc+2][ldr]    = a0.z; As[bf][ldc+3][ldr]    = a0.w;                 \
    As[bf][ldc+0][ldr+64] = a1.x; As[bf][ldc+1][ldr+64] = a1.y;                 \
    As[bf][ldc+2][ldr+64] = a1.z; As[bf][ldc+3][ldr+64] = a1.w;                 \
    Bs[bf][ldc+0][ldr]    = b0.x; Bs[bf][ldc+1][ldr]    = b0.y;                 \
    Bs[bf][ldc+2][ldr]    = b0.z; Bs[bf][ldc+3][ldr]    = b0.w;                 \
    Bs[bf][ldc+0][ldr+64] = b1.x; Bs[bf][ldc+1][ldr+64] = b1.y;                 \
    Bs[bf][ldc+2][ldr+64] = b1.z; Bs[bf][ldc+3][ldr+64] = b1.w; }

#define COMPUTE(bf) {                                                           \
    _Pragma("unroll")                                                           \
    for (int k = 0; k < 16; k++) {                                              \
        float4 av0 = *(const float4*)&As[bf][k][ry];                            \
        float4 av1 = *(const float4*)&As[bf][k][ry + 4];                        \
        float4 bv0 = *(const float4*)&Bs[bf][k][rx];                            \
        float4 bv1 = *(const float4*)&Bs[bf][k][rx + 4];                        \
        u64t bp[4];                                                             \
        bp[0] = ((const u64t*)&bv0)[0]; bp[1] = ((const u64t*)&bv0)[1];         \
        bp[2] = ((const u64t*)&bv1)[0]; bp[3] = ((const u64t*)&bv1)[1];         \
        float a[8] = {av0.x,av0.y,av0.z,av0.w,av1.x,av1.y,av1.z,av1.w};         \
        _Pragma("unroll")                                                       \
        for (int i = 0; i < 8; i++) {                                           \
            u64t ai = bcast2(a[i]);                                             \
            fma2(acc2[i][0], ai, bp[0]);                                        \
            fma2(acc2[i][1], ai, bp[1]);                                        \
            fma2(acc2[i][2], ai, bp[2]);                                        \
            fma2(acc2[i][3], ai, bp[3]);                                        \
        }                                                                       \
    } }

    LOADG(0);
    STORES(0);
    __syncthreads();
    int buf = 0;
    for (int k0 = 16; k0 < K; k0 += 16) {
        LOADG(k0);
        COMPUTE(buf);
        STORES(buf ^ 1);
        __syncthreads();
        buf ^= 1;
    }
    COMPUTE(buf);

#undef LOADG
#undef STORES
#undef COMPUTE

    // unpack + threshold
    float acc[8][8];
    #pragma unroll
    for (int i = 0; i < 8; i++)
        #pragma unroll
        for (int jp = 0; jp < 4; jp++) {
            float2 v = unpack2(acc2[i][jp]);
            acc[i][2 * jp + 0] = thrf(v.x, scale, th);
            acc[i][2 * jp + 1] = thrf(v.y, scale, th);
        }

    #pragma unroll
    for (int i = 0; i < 8; i++) {
        #pragma unroll
        for (int j = 0; j < 8; j += 4) {
            float4 v = make_float4(acc[i][j], acc[i][j+1], acc[i][j+2], acc[i][j+3]);
            *(float4*)(C + (size_t)(m0 + ry + i) * N + (n0 + rx + j)) = v;
        }
    }
    if (bx > by) {
        #pragma unroll
        for (int j = 0; j < 8; j++) {
            #pragma unroll
            for (int i = 0; i < 8; i += 4) {
                float4 v = make_float4(acc[i][j], acc[i+1][j], acc[i+2][j], acc[i+3][j]);
                *(float4*)(C + (size_t)(n0 + rx + j) * N + (m0 + ry + i)) = v;
            }
        }
    }

    if (csPart) {
        __syncthreads();
        float* red = (float*)As;
        #pragma unroll
        for (int jj = 0; jj < 8; jj++) {
            float s = 0.f;
            #pragma unroll
            for (int i = 0; i < 8; i++) s += acc[i][jj];
            red[ty * 128 + rx + jj] = s;
        }
        __syncthreads();
        if (tid < 128) {
            float s = 0.f;
            #pragma unroll
            for (int p = 0; p < 16; p++) s += red[p * 128 + tid];
            csPart[(size_t)by * N + n0 + tid] = s;
        }
        if (bx > by) {
            __syncthreads();
            #pragma unroll
            for (int ii = 0; ii < 8; ii++) {
                float s = 0.f;
                #pragma unroll
                for (int j = 0; j < 8; j++) s += acc[ii][j];
                red[tx * 128 + ry + ii] = s;
            }
            __syncthreads();
            if (tid < 128) {
                float s = 0.f;
                #pragma unroll
                for (int p = 0; p < 16; p++) s += red[p * 128 + tid];
                csPart[(size_t)bx * N + m0 + tid] = s;
            }
        }
    }
}

// Deterministic ballot-compacted nonzero index list per target row of an adjacency block.
__global__ void build_idx_kernel(const float* __restrict__ adj, int col_off, int NR,
                                 int* __restrict__ idx, int* __restrict__ cnt)
{
    int i = blockIdx.x;
    const float* r = adj + (size_t)i * NALL + col_off;
    int lane = threadIdx.x;
    int count = 0;
    for (int base = 0; base < NR; base += 32) {
        float v = r[base + lane];
        unsigned m = __ballot_sync(0xffffffffu, v != 0.f);
        int pre = __popc(m & ((1u << lane) - 1u));
        if (v != 0.f && (count + pre) < CAP) idx[(size_t)i * CAP + count + pre] = base + lane;
        count += __popc(m);
    }
    if (lane == 0) cnt[i] = min(count, CAP);
}

__global__ void gather_sum_kernel(const float* __restrict__ src, int lds,
                                  const int* __restrict__ idx, const int* __restrict__ cnt,
                                  float* __restrict__ out, int ldo)
{
    int i = blockIdx.y;
    int j = ((blockIdx.x * blockDim.x + threadIdx.x) << 2);
    int c = cnt[i];
    const int* ip = idx + (size_t)i * CAP;
    float4 s = make_float4(0.f, 0.f, 0.f, 0.f);
    for (int t = 0; t < c; t++) {
        float4 v = *(const float4*)(src + (size_t)ip[t] * lds + j);
        s.x += v.x; s.y += v.y; s.z += v.z; s.w += v.w;
    }
    *(float4*)(out + (size_t)i * ldo + j) = s;
}

__global__ void gather64b_kernel(const float* __restrict__ src,
                                 const int* __restrict__ idx, const int* __restrict__ cnt,
                                 const float* __restrict__ bias, float* __restrict__ out)
{
    int i = blockIdx.x;
    int c = threadIdx.x;
    int n = cnt[i];
    const int* ip = idx + (size_t)i * CAP;
    float s = 0.f;
    for (int t = 0; t < n; t++) s += src[(size_t)ip[t] * 64 + c];
    out[(size_t)i * 64 + c] = s + bias[c];
}

// C[M,64] = A[M,K] @ B[K,64] (+bias) (optional relu) — f32x2 inner, 4x8 warp map
__global__ void __launch_bounds__(256)
gemm_n64_kernel(const float* __restrict__ A, const float* __restrict__ B,
                const float* __restrict__ bias, float* __restrict__ C,
                int M, int K, int relu)
{
    __shared__ float As[32][64];
    __shared__ float Bs[32][64];
    int tid = threadIdx.x;
    int m0  = blockIdx.x * 64;
    int ar  = tid >> 3;
    int ac  = (tid & 7) << 2;
    int br  = tid >> 4;
    int bc  = (tid & 15) << 2;
    int wrp = tid >> 5, ln = tid & 31;
    int ty  = ((wrp >> 1) << 2) | (ln >> 3);
    int tx  = ((wrp & 1) << 3) | (ln & 7);

    u64t acc2[4][2];
    #pragma unroll
    for (int i = 0; i < 4; i++) { acc2[i][0] = 0ull; acc2[i][1] = 0ull; }

    for (int k0 = 0; k0 < K; k0 += 32) {
        float4 a0 = *(const float4*)(A + (size_t)(m0 + ar)      * K + k0 + ac);
        float4 a1 = *(const float4*)(A + (size_t)(m0 + ar + 32) * K + k0 + ac);
        float4 b0 = *(const float4*)(B + (size_t)(k0 + br)      * 64 + bc);
        float4 b1 = *(const float4*)(B + (size_t)(k0 + br + 16) * 64 + bc);
        __syncthreads();
        As[ac+0][ar]    = a0.x; As[ac+1][ar]    = a0.y; As[ac+2][ar]    = a0.z; As[ac+3][ar]    = a0.w;
        As[ac+0][ar+32] = a1.x; As[ac+1][ar+32] = a1.y; As[ac+2][ar+32] = a1.z; As[ac+3][ar+32] = a1.w;
        *(float4*)&Bs[br][bc]      = b0;
        *(float4*)&Bs[br + 16][bc] = b1;
        __syncthreads();
        #pragma unroll
        for (int k = 0; k < 32; k++) {
            float4 av = *(const float4*)&As[k][ty << 2];
            float4 bv = *(const float4*)&Bs[k][tx << 2];
            u64t bp0 = ((const u64t*)&bv)[0], bp1 = ((const u64t*)&bv)[1];
            float a[4] = {av.x, av.y, av.z, av.w};
            #pragma unroll
            for (int i = 0; i < 4; i++) {
                u64t ai = bcast2(a[i]);
                fma2(acc2[i][0], ai, bp0);
                fma2(acc2[i][1], ai, bp1);
            }
        }
    }
    int r = m0 + (ty << 2), c = tx << 2;
    #pragma unroll
    for (int i = 0; i < 4; i++) {
        float2 v0 = unpack2(acc2[i][0]);
        float2 v1 = unpack2(acc2[i][1]);
        float vv[4] = {v0.x, v0.y, v1.x, v1.y};
        #pragma unroll
        for (int j = 0; j < 4; j++) {
            float v = vv[j] + (bias ? bias[c + j] : 0.f);
            if (relu) v = fmaxf(v, 0.f);
            C[(size_t)(r + i) * 64 + c + j] = v;
        }
    }
}

// split-K variant: grid (M/64, S)
__global__ void __launch_bounds__(256)
gemm_n64_splitk_kernel(const float* __restrict__ A, const float* __restrict__ B,
                       float* __restrict__ part, int M, int K, int Kc)
{
    __shared__ float As[32][64];
    __shared__ float Bs[32][64];
    int tid = threadIdx.x;
    int m0  = blockIdx.x * 64;
    int s   = blockIdx.y;
    int kb  = s * Kc, ke = kb + Kc;
    int ar  = tid >> 3;
    int ac  = (tid & 7) << 2;
    int br  = tid >> 4;
    int bc  = (tid & 15) << 2;
    int wrp = tid >> 5, ln = tid & 31;
    int ty  = ((wrp >> 1) << 2) | (ln >> 3);
    int tx  = ((wrp & 1) << 3) | (ln & 7);

    u64t acc2[4][2];
    #pragma unroll
    for (int i = 0; i < 4; i++) { acc2[i][0] = 0ull; acc2[i][1] = 0ull; }

    for (int k0 = kb; k0 < ke; k0 += 32) {
        float4 a0 = *(const float4*)(A + (size_t)(m0 + ar)      * K + k0 + ac);
        float4 a1 = *(const float4*)(A + (size_t)(m0 + ar + 32) * K + k0 + ac);
        float4 b0 = *(const float4*)(B + (size_t)(k0 + br)      * 64 + bc);
        float4 b1 = *(const float4*)(B + (size_t)(k0 + br + 16) * 64 + bc);
        __syncthreads();
        As[ac+0][ar]    = a0.x; As[ac+1][ar]    = a0.y; As[ac+2][ar]    = a0.z; As[ac+3][ar]    = a0.w;
        As[ac+0][ar+32] = a1.x; As[ac+1][ar+32] = a1.y; As[ac+2][ar+32] = a1.z; As[ac+3][ar+32] = a1.w;
        *(float4*)&Bs[br][bc]      = b0;
        *(float4*)&Bs[br + 16][bc] = b1;
        __syncthreads();
        #pragma unroll
        for (int k = 0; k < 32; k++) {
            float4 av = *(const float4*)&As[k][ty << 2];
            float4 bv = *(const float4*)&Bs[k][tx << 2];
            u64t bp0 = ((const u64t*)&bv)[0], bp1 = ((const u64t*)&bv)[1];
            float a[4] = {av.x, av.y, av.z, av.w};
            #pragma unroll
            for (int i = 0; i < 4; i++) {
                u64t ai = bcast2(a[i]);
                fma2(acc2[i][0], ai, bp0);
                fma2(acc2[i][1], ai, bp1);
            }
        }
    }
    int r = m0 + (ty << 2), c = tx << 2;
    #pragma unroll
    for (int i = 0; i < 4; i++) {
        float2 v0 = unpack2(acc2[i][0]);
        float2 v1 = unpack2(acc2[i][1]);
        float vv[4] = {v0.x, v0.y, v1.x, v1.y};
        #pragma unroll
        for (int j = 0; j < 4; j++)
            part[(size_t)s * M * 64 + (size_t)(r + i) * 64 + c + j] = vv[j];
    }
}

__global__ void splitk_reduce_kernel(const float* __restrict__ part, const float* __restrict__ bias,
                                     float* __restrict__ C, int M, int S, int relu)
{
    int idx = blockIdx.x * 256 + threadIdx.x;
    if (idx >= M * 64) return;
    float s = 0.f;
    for (int p = 0; p < S; p++) s += part[(size_t)p * M * 64 + idx];
    if (bias) s += bias[idx & 63];
    if (relu) s = fmaxf(s, 0.f);
    C[idx] = s;
}

__global__ void cs_reduce_kernel(const float* __restrict__ CSP, float* __restrict__ CS)
{
    int m = blockIdx.y;
    int j = blockIdx.x * 256 + threadIdx.x;
    float s = 0.f;
    #pragma unroll
    for (int p = 0; p < 32; p++) s += CSP[((size_t)m * 32 + p) * NT + j];
    CS[m * NT + j] = s;
}

__global__ void coefs_kernel(const float* __restrict__ sgw, const float* __restrict__ ffw,
                             const float* __restrict__ f4w,
                             const float* __restrict__ cs, float* __restrict__ coef,
                             float* __restrict__ ct0)
{
    int j = blockIdx.x * 256 + threadIdx.x;
    float m2 = fmaxf(sgw[0], sgw[1]);
    float e0 = expf(sgw[0] - m2), e1 = expf(sgw[1] - m2);
    float sa0 = e0 / (e0 + e1), sa1 = e1 / (e0 + e1);
    float mf = fmaxf(ffw[0], ffw[1]);
    float f0 = expf(ffw[0] - mf), f1 = expf(ffw[1] - mf);
    float fa0 = f0 / (f0 + f1), fa1 = f1 / (f0 + f1);
    float m4 = fmaxf(fmaxf(f4w[0], f4w[1]), fmaxf(f4w[2], f4w[3]));
    float w0 = expf(f4w[0] - m4), w1 = expf(f4w[1] - m4), w2 = expf(f4w[2] - m4), w3 = expf(f4w[3] - m4);
    float ws = w0 + w1 + w2 + w3;
    w0 /= ws; w1 /= ws; w2 /= ws; w3 /= ws;

    float csv[7], cf[7];
    #pragma unroll
    for (int m = 0; m < 7; m++) csv[m] = cs[m * NT + j];
    float uP  = (csv[1] > 0.05f) ? 1.f : 0.f;
    float uQ  = (csv[2] > 0.05f) ? 1.f : 0.f;
    float uFA = (csv[3] > 0.05f) ? 1.f : 0.f;
    float uFS = (csv[4] > 0.05f) ? 1.f : 0.f;
    float uSA = (csv[5] > 0.05f) ? 1.f : 0.f;
    float uSS = (csv[6] > 0.05f) ? 1.f : 0.f;
    float dSem = fmaxf(sa0 * uP  + sa1 * uQ,  1e-12f);
    float dFp  = fmaxf(fa0 * uFA + fa1 * uFS, 1e-12f);
    float dSt  = fmaxf(fa0 * uSA + fa1 * uSS, 1e-12f);

    cf[0] = w0 / fmaxf(csv[0], 1e-12f);
    cf[1] = w1 * sa0 / (fmaxf(csv[1], 1e-12f) * dSem);
    cf[2] = w1 * sa1 / (fmaxf(csv[2], 1e-12f) * dSem);
    cf[3] = w2 * fa0 / (fmaxf(csv[3], 1e-12f) * dFp);
    cf[4] = w2 * fa1 / (fmaxf(csv[4], 1e-12f) * dFp);
    cf[5] = w3 * fa0 / (fmaxf(csv[5], 1e-12f) * dSt);
    cf[6] = w3 * fa1 / (fmaxf(csv[6], 1e-12f) * dSt);

    float c0 = 0.f;
    #pragma unroll
    for (int m = 0; m < 7; m++) { coef[m * NT + j] = cf[m]; c0 += cf[m] * csv[m]; }
    ct0[j] = c0;
}

__global__ void combine_kernel(const float* __restrict__ G,  const float* __restrict__ P,
                               const float* __restrict__ Q,  const float* __restrict__ FA,
                               const float* __restrict__ FS, const float* __restrict__ SA,
                               const float* __restrict__ SS, const float* __restrict__ coef,
                               float* __restrict__ out, float* __restrict__ rowp)
{
    int b = blockIdx.x;
    size_t e = ((size_t)b * 256 + threadIdx.x) << 2;
    int j = (int)(e & (NT - 1));
    float4 r = make_float4(0.f, 0.f, 0.f, 0.f);
#define ACC(buf, m) { float4 v = *(const float4*)((buf) + e);                 \
                      float4 k = *(const float4*)(coef + (m) * NT + j);       \
                      r.x = fmaf(k.x, v.x, r.x); r.y = fmaf(k.y, v.y, r.y);   \
                      r.z = fmaf(k.z, v.z, r.z); r.w = fmaf(k.w, v.w, r.w); }
    ACC(G, 0) ACC(P, 1) ACC(Q, 2) ACC(FA, 3) ACC(FS, 4) ACC(SA, 5) ACC(SS, 6)
#undef ACC
    *(float4*)(out + e) = r;

    float s = r.x + r.y + r.z + r.w;
    #pragma unroll
    for (int o = 16; o; o >>= 1) s += __shfl_xor_sync(0xffffffffu, s, o);
    __shared__ float ws[8];
    int w = threadIdx.x >> 5;
    if ((threadIdx.x & 31) == 0) ws[w] = s;
    __syncthreads();
    if (threadIdx.x == 0) {
        float t = 0.f;
        #pragma unroll
        for (int p = 0; p < 8; p++) t += ws[p];
        rowp[(size_t)(b >> 2) * 4 + (b & 3)] = t;
    }
}

__global__ void ct_final_kernel(const float* __restrict__ ct0, const float* __restrict__ rowp,
                                float* __restrict__ ct)
{
    int j = blockIdx.x * 256 + threadIdx.x;
    ct[j] = ct0[j] + rowp[j * 4 + 0] + rowp[j * 4 + 1] + rowp[j * 4 + 2] + rowp[j * 4 + 3];
}

__global__ void symscale_kernel(float* __restrict__ A, const float* __restrict__ ct)
{
    const int nb = 128;
    int idx = blockIdx.x;
    float nb2 = nb + 0.5f;
    int bi = (int)(nb2 - sqrtf(fmaxf(nb2 * nb2 - 2.0f * idx, 0.f)));
    if (bi < 0) bi = 0;
    if (bi > nb - 1) bi = nb - 1;
    while (bi > 0 && (bi * nb - (bi * (bi - 1)) / 2) > idx) bi--;
    while (((bi + 1) * nb - ((bi + 1) * bi) / 2) <= idx) bi++;
    int bj = bi + (idx - (bi * nb - (bi * (bi - 1)) / 2));

    __shared__ float T1[32][33], T2[32][33];
    int x = threadIdx.x, y0 = threadIdx.y;
    for (int y = y0; y < 32; y += 8) T1[y][x] = A[(size_t)(bi * 32 + y) * NT + bj * 32 + x];
    if (bi != bj)
        for (int y = y0; y < 32; y += 8) T2[y][x] = A[(size_t)(bj * 32 + y) * NT + bi * 32 + x];
    __syncthreads();
    float cj = fmaxf(ct[bj * 32 + x], 1e-12f);
    if (bi == bj) {
        for (int y = y0; y < 32; y += 8)
            A[(size_t)(bi * 32 + y) * NT + bj * 32 + x] = (T1[y][x] + T1[x][y]) / cj;
    } else {
        float ci = fmaxf(ct[bi * 32 + x], 1e-12f);
        for (int y = y0; y < 32; y += 8)
            A[(size_t)(bi * 32 + y) * NT + bj * 32 + x] = (T1[y][x] + T2[x][y]) / cj;
        for (int y = y0; y < 32; y += 8)
            A[(size_t)(bj * 32 + y) * NT + bi * 32 + x] = (T2[y][x] + T1[x][y]) / ci;
    }
}

__global__ void x1w2_kernel(const float* __restrict__ X1, const float* __restrict__ W2,
                            float* __restrict__ H2)
{
    int i = blockIdx.x * 256 + threadIdx.x;
    if (i >= NT) return;
    float s0 = 0.f, s1 = 0.f, s2 = 0.f;
    #pragma unroll 8
    for (int k = 0; k < COM; k++) {
        float x = X1[(size_t)i * COM + k];
        s0 = fmaf(x, W2[k * 3 + 0], s0);
        s1 = fmaf(x, W2[k * 3 + 1], s1);
        s2 = fmaf(x, W2[k * 3 + 2], s2);
    }
    H2[i * 3 + 0] = s0; H2[i * 3 + 1] = s1; H2[i * 3 + 2] = s2;
}

__global__ void logits_kernel(const float* __restrict__ A, const float* __restrict__ H2,
                              const float* __restrict__ b2, float* __restrict__ out)
{
    int i = blockIdx.x, tid = threadIdx.x;
    const float* row = A + (size_t)i * NT;
    float s0 = 0.f, s1 = 0.f, s2 = 0.f;
    for (int k = tid; k < NT; k += 256) {
        float a = row[k];
        s0 = fmaf(a, H2[k * 3 + 0], s0);
        s1 = fmaf(a, H2[k * 3 + 1], s1);
        s2 = fmaf(a, H2[k * 3 + 2], s2);
    }
    #pragma unroll
    for (int o = 16; o; o >>= 1) {
        s0 += __shfl_xor_sync(0xffffffffu, s0, o);
        s1 += __shfl_xor_sync(0xffffffffu, s1, o);
        s2 += __shfl_xor_sync(0xffffffffu, s2, o);
    }
    __shared__ float sh[3][8];
    int w = tid >> 5, l = tid & 31;
    if (l == 0) { sh[0][w] = s0; sh[1][w] = s1; sh[2][w] = s2; }
    __syncthreads();
    if (tid == 0) {
        float x0 = 0.f, x1 = 0.f, x2 = 0.f;
        #pragma unroll
        for (int t = 0; t < 8; t++) { x0 += sh[0][t]; x1 += sh[1][t]; x2 += sh[2][t]; }
        x0 += b2[0]; x1 += b2[1]; x2 += b2[2];
        float m  = fmaxf(x0, fmaxf(x1, x2));
        float ls = logf(expf(x0 - m) + expf(x1 - m) + expf(x2 - m));
        out[i * 3 + 0] = x0 - m - ls;
        out[i * 3 + 1] = x1 - m - ls;
        out[i * 3 + 2] = x2 - m - ls;
    }
}

// ---------------- host orchestration ----------------------------------------

extern "C" void kernel_launch(void* const* d_in, const int* in_sizes, int n_in,
                              void* d_out, int out_size)
{
    const float* features  = (const float*)d_in[0];
    const float* adj_ori   = (const float*)d_in[1];
    const float* mp_pap    = (const float*)d_in[2];
    const float* mp_psp    = (const float*)d_in[3];
    const float* fgo_w     = (const float*)d_in[6];
    const float* fpo_w     = (const float*)d_in[7];
    const float* sgg_pap_w = (const float*)d_in[8];
    const float* sgg_psp_w = (const float*)d_in[9];
    const float* sg_agg_w  = (const float*)d_in[10];
    const float* f_agg_f_w = (const float*)d_in[11];
    const float* f_agg_w   = (const float*)d_in[12];
    const float* topo_W_a  = (const float*)d_in[13];
    const float* topo_b_a  = (const float*)d_in[14];
    const float* topo_W_s  = (const float*)d_in[15];
    const float* topo_b_s  = (const float*)d_in[16];
    const float* fgt_w_a   = (const float*)d_in[17];
    const float* fgt_w_s   = (const float*)d_in[18];
    const float* gcn_W1    = (const float*)d_in[19];
    const float* gcn_b1    = (const float*)d_in[20];
    const float* gcn_W2    = (const float*)d_in[21];
    const float* gcn_b2    = (const float*)d_in[22];
    (void)in_sizes; (void)n_in; (void)out_size;

    float* out   = (float*)d_out;
    float* NAdj  = out + (size_t)NT * NCLS;

    float* big = nullptr; float* sm = nullptr; int* ib = nullptr;
    cudaGetSymbolAddress((void**)&big, g_big);
    cudaGetSymbolAddress((void**)&sm,  g_small);
    cudaGetSymbolAddress((void**)&ib,  g_ibuf);

    float* G   = big + 0ll * NT * NT;
    float* P   = big + 1ll * NT * NT;
    float* Q   = big + 2ll * NT * NT;
    float* FAb = big + 3ll * NT * NT;
    float* FSb = big + 4ll * NT * NT;
    float* SAb = big + 5ll * NT * NT;
    float* SSb = big + 6ll * NT * NT;

    float* XN    = sm + OFF_XN;
    float* SIMS  = sm + OFF_SIMS;
    float* FPA   = sm + OFF_FPA;
    float* FPS   = sm + OFF_FPS;
    float* THA   = sm + OFF_THA;
    float* THS   = sm + OFF_THS;
    float* SWA   = sm + OFF_SWA;
    float* SWS   = sm + OFF_SWS;
    float* H0    = sm + OFF_H0;
    float* X1    = sm + OFF_X1;
    float* H2    = sm + OFF_H2;
    float* CS    = sm + OFF_CS;
    float* COEF  = sm + OFF_COEF;
    float* CT0   = sm + OFF_CT0;
    float* CT    = sm + OFF_CT;
    float* ROWP  = sm + OFF_ROWP;
    float* CSP   = sm + OFF_CSP;
    float* SPART = sm + OFF_SPART;

    int* IDXA = ib + OFF_IDXA; int* CNTA = ib + OFF_CNTA;
    int* IDXS = ib + OFF_IDXS; int* CNTS = ib + OFF_CNTS;

    const int TRI32 = 32 * 33 / 2;
    const int TRI8  = 8 * 9 / 2;
    dim3 bSym(32, 8);

    // ---- g_targ / sem_pap / sem_psp ----
    prep_norm_kernel<<<NT / 4, 128>>>(features, fgo_w, XN, NT, FEAT, 2);
    simgemm_kernel<<<TRI32, 256>>>(XN, G, NT, 256, 0.5f, 0.1f, CSP + 0ll * 32 * NT, 32);
    prep_norm_kernel<<<NT / 4, 128>>>(mp_pap, sgg_pap_w, XN, NT, MPD, 2);
    simgemm_kernel<<<TRI32, 256>>>(XN, P, NT, 128, 0.5f, 0.1f, CSP + 1ll * 32 * NT, 32);
    prep_norm_kernel<<<NT / 4, 128>>>(mp_psp, sgg_psp_w, XN, NT, MPD, 2);
    simgemm_kernel<<<TRI32, 256>>>(XN, Q, NT, 128, 0.5f, 0.1f, CSP + 2ll * 32 * NT, 32);

    // ---- relation A ----
    prep_norm_kernel<<<NT / 4, 128>>>(features + (size_t)NT * FEAT, fgo_w, XN, NAr, FEAT, 2);
    simgemm_kernel<<<TRI32, 256>>>(XN, SAb, NAr, 256, 0.5f, 0.1f, nullptr, 32);
    build_idx_kernel<<<NT, 32>>>(adj_ori, NT, NAr, IDXA, CNTA);
    gemm_n64_splitk_kernel<<<dim3(NT / 64, 8), 256>>>(SAb, topo_W_a, SPART, NT, NAr, NAr / 8);
    splitk_reduce_kernel<<<(NT * 64) / 256, 256>>>(SPART, nullptr, SWA, NT, 8, 0);
    gather64b_kernel<<<NT, 64>>>(SWA, IDXA, CNTA, topo_b_a, THA);
    gather_sum_kernel<<<dim3(1, NT), 32>>>(features + (size_t)NT * FEAT, FEAT, IDXA, CNTA, FPA, FEAT);
    prep_norm_kernel<<<NT / 4, 128>>>(FPA, fpo_w, XN, NT, FEAT, 2);
    simgemm_kernel<<<TRI32, 256>>>(XN, FAb, NT, 256, 0.5f, 0.2f, CSP + 3ll * 32 * NT, 32);
    prep_norm_kernel<<<NT / 4, 128>>>(THA, fgt_w_a, XN, NT, COM, 2);
    simgemm_kernel<<<TRI32, 256>>>(XN, SAb, NT, 128, 0.5f, 0.1f, CSP + 5ll * 32 * NT, 32);

    // ---- relation S ----
    prep_norm_kernel<<<NSr / 4, 128>>>(features + (size_t)(NT + NAr) * FEAT, fgo_w, XN, NSr, FEAT, 2);
    simgemm_kernel<<<TRI8, 256>>>(XN, SIMS, NSr, 256, 0.5f, 0.1f, nullptr, 8);
    build_idx_kernel<<<NT, 32>>>(adj_ori, NT + NAr, NSr, IDXS, CNTS);
    gemm_n64_splitk_kernel<<<dim3(NSr / 64, 8), 256>>>(SIMS, topo_W_s, SPART, NSr, NSr, NSr / 8);
    splitk_reduce_kernel<<<(NSr * 64) / 256, 256>>>(SPART, nullptr, SWS, NSr, 8, 0);
    gather64b_kernel<<<NT, 64>>>(SWS, IDXS, CNTS, topo_b_s, THS);
    gather_sum_kernel<<<dim3(1, NT), 32>>>(features + (size_t)(NT + NAr) * FEAT, FEAT, IDXS, CNTS, FPS, FEAT);
    prep_norm_kernel<<<NT / 4, 128>>>(FPS, fpo_w, XN, NT, FEAT, 2);
    simgemm_kernel<<<TRI32, 256>>>(XN, FSb, NT, 256, 0.5f, 0.2f, CSP + 4ll * 32 * NT, 32);
    prep_norm_kernel<<<NT / 4, 128>>>(THS, fgt_w_s, XN, NT, COM, 2);
    simgemm_kernel<<<TRI32, 256>>>(XN, SSb, NT, 128, 0.5f, 0.1f, CSP + 6ll * 32 * NT, 32);

    // ---- fused channel attention ----
    cs_reduce_kernel<<<dim3(NT / 256, 7), 256>>>(CSP, CS);
    coefs_kernel<<<NT / 256, 256>>>(sg_agg_w, f_agg_f_w, f_agg_w, CS, COEF, CT0);
    combine_kernel<<<(NT * NT) / 1024, 256>>>(G, P, Q, FAb, FSb, SAb, SSb, COEF, NAdj, ROWP);
    ct_final_kernel<<<NT / 256, 256>>>(CT0, ROWP, CT);
    symscale_kernel<<<128 * 129 / 2, bSym>>>(NAdj, CT);

    // ---- GCN ----
    gemm_n64_kernel<<<NT / 64, 256>>>(features, gcn_W1, nullptr, H0, NT, FEAT, 0);
    gemm_n64_splitk_kernel<<<dim3(NT / 64, 8), 256>>>(NAdj, H0, SPART, NT, NT, NT / 8);
    splitk_reduce_kernel<<<(NT * 64) / 256, 256>>>(SPART, gcn_b1, X1, NT, 8, 1);
    x1w2_kernel<<<NT / 256, 256>>>(X1, gcn_W2, H2);
    logits_kernel<<<NT, 256>>>(NAdj, H2, gcn_b2, out);
}